// round 13
// baseline (speedup 1.0000x reference)
#include <cuda_runtime.h>
#include <cuda_fp16.h>
#include <math.h>
#include <stdint.h>

// ---------------- problem constants ----------------
#define NB   16
#define NV   2048
#define NRC  32
#define NSC  256
#define NEC  512
#define NOUT 12
#define NLAY 8
#define NN   (NV*NV)
#define XBUF (NB*NRC*13*NV)
#define HBUF (NB*NRC*12*NV)

// ---------------- device scratch ----------------
__device__ float  g_adp [NN];
__device__ __half g_bt  [3*NN];          // fp16 transposed supports [z][n][k]
__device__ float  g_xa  [XBUF];
__device__ float  g_xb  [XBUF];
__device__ __half g_gx  [HBUF];
__device__ __half g_H   [6*HBUF];
__device__ __half g_gxl [NB*NV*NSC];     // last-timestep gated outs [bv][l*32+c]
__device__ __half g_wsk [NSC*NSC];       // stacked skip weights [j][l*32+c]
__device__ float  g_bsk [NSC];           // summed skip bias
__device__ __half g_skt [NB*NV*NSC];     // relu'd skip, [bv][j] fp16
__device__ float  g_e1  [NB*NV*NEC];
__device__ __half g_w1r [NEC*NSC];       // fp16 e1w, already [n][k]
__device__ float  g_wgt [NLAY*224*32];   // gcn weights pre-transposed [l][gc][og*8+j]
__device__ __half g_wf  [NLAY*64*64];    // gated weights [l][q=2o+isg][k=2c+tap]

// ---------------- helpers ----------------
__device__ __forceinline__ float tanh_fast(float x) {
    float y; asm("tanh.approx.f32 %0, %1;" : "=f"(y) : "f"(x));
    return y;
}
__device__ __forceinline__ uint32_t smem_u32(const void* p) {
    uint32_t a;
    asm("{ .reg .u64 t; cvta.to.shared.u64 t, %1; cvt.u32.u64 %0, t; }" : "=r"(a) : "l"(p));
    return a;
}
__device__ __forceinline__ void cp_async16(uint32_t dst, const void* src) {
    asm volatile("cp.async.cg.shared.global [%0], [%1], 16;" :: "r"(dst), "l"(src));
}
#define CP_COMMIT() asm volatile("cp.async.commit_group;" ::: "memory")

__device__ __forceinline__ void mma_f16_16x8x16(
    float& d0, float& d1, float& d2, float& d3,
    uint32_t a0, uint32_t a1, uint32_t a2, uint32_t a3,
    uint32_t b0, uint32_t b1)
{
    asm volatile(
        "mma.sync.aligned.m16n8k16.row.col.f32.f16.f16.f32 "
        "{%0,%1,%2,%3}, {%4,%5,%6,%7}, {%8,%9}, {%0,%1,%2,%3};"
        : "+f"(d0), "+f"(d1), "+f"(d2), "+f"(d3)
        : "r"(a0), "r"(a1), "r"(a2), "r"(a3), "r"(b0), "r"(b1));
}
__device__ __forceinline__ void ldsm_x4(
    uint32_t& r0, uint32_t& r1, uint32_t& r2, uint32_t& r3, uint32_t addr)
{
    asm volatile("ldmatrix.sync.aligned.m8n8.x4.shared.b16 {%0,%1,%2,%3}, [%4];"
        : "=r"(r0), "=r"(r1), "=r"(r2), "=r"(r3) : "r"(addr));
}

// ---------------- fp16 HMMA GEMM: C[M,N] = X[M,K] @ B[N,K]^T ----------------
// CTA tile 256x128, BK=64, 512 threads = 16 warps (8m x 2n), warp tile 32x64.
// 3-stage cp.async, register double-buffered ldmatrix fragments (R11 mainloop).
// flags: bit0 relu, bit2 fp16 out.
#define BM 256
#define BN 128
#define BK 64
#define NTHR 512
#define KPAD_H 72
#define STG_A (256*KPAD_H)
#define STG_B (128*KPAD_H)
#define STG_T (STG_A + STG_B)
#define NSTAGE 3
#define GSMEM (NSTAGE*STG_T*2)

__global__ void __launch_bounds__(NTHR) mma_gemm(
    const __half* __restrict__ X, const __half* __restrict__ B, void* __restrict__ Cv,
    long sX, long sB, long sC,
    int lda, int ldb, int ldc, int nkt,
    const float* __restrict__ bias, int flags)
{
    extern __shared__ __half sm[];

    int z = blockIdx.z;
    X += (size_t)z*sX;
    B += (size_t)z*sB;
    int m0 = blockIdx.y*BM, n0 = blockIdx.x*BN;

    int tid = threadIdx.x, wid = tid >> 5, lane = tid & 31;
    int wm = wid & 7, wn = wid >> 3;          // 8 m-warps x 2 n-warps
    int lq = lane >> 2, lr = lane & 3;
    int lane15 = lane & 15, laneh = lane >> 4;

    uint32_t sbase = smem_u32(sm);

    auto load_stage = [&](int s, int k0) {
        uint32_t da = sbase + (uint32_t)(s*STG_T)*2;
        uint32_t db = da + (uint32_t)STG_A*2;
        const __half* xs = X + (size_t)m0*lda + k0;
        const __half* bs = B + (size_t)n0*ldb + k0;
        #pragma unroll
        for (int i = 0; i < 4; i++) {
            int l = tid + i*NTHR;              // 0..2047 (A: 256 rows x 8 segs)
            int row = l >> 3, seg = l & 7;
            uint32_t off = (uint32_t)(row*KPAD_H + seg*8)*2;
            cp_async16(da + off, xs + (size_t)row*lda + seg*8);
        }
        #pragma unroll
        for (int i = 0; i < 2; i++) {
            int l = tid + i*NTHR;              // 0..1023 (B: 128 rows x 8 segs)
            int row = l >> 3, seg = l & 7;
            uint32_t off = (uint32_t)(row*KPAD_H + seg*8)*2;
            cp_async16(db + off, bs + (size_t)row*ldb + seg*8);
        }
    };

    float acc[2][8][4];
    #pragma unroll
    for (int mt = 0; mt < 2; mt++)
        #pragma unroll
        for (int nt = 0; nt < 8; nt++)
            #pragma unroll
            for (int k = 0; k < 4; k++) acc[mt][nt][k] = 0.f;

    load_stage(0, 0);  CP_COMMIT();
    if (nkt > 1) load_stage(1, BK);
    CP_COMMIT();

    uint32_t aoff0 = (uint32_t)((wm*32 + lane15)*KPAD_H + 8*laneh);
    uint32_t aoff1 = aoff0 + 16u*KPAD_H;
    uint32_t boff  = (uint32_t)(STG_A + (wn*64 + lane15)*KPAD_H + 8*laneh);

    for (int kt = 0; kt < nkt; kt++) {
        asm volatile("cp.async.wait_group 1;" ::: "memory");
        __syncthreads();

        if (kt + 2 < nkt) load_stage((kt+2) % NSTAGE, (kt+2)*BK);
        CP_COMMIT();

        uint32_t slab = sbase + (uint32_t)((kt % NSTAGE)*STG_T)*2;

        uint32_t a[2][2][4], b[2][8][2];
        ldsm_x4(a[0][0][0], a[0][0][1], a[0][0][2], a[0][0][3], slab + aoff0*2);
        ldsm_x4(a[0][1][0], a[0][1][1], a[0][1][2], a[0][1][3], slab + aoff1*2);
        #pragma unroll
        for (int nt2 = 0; nt2 < 4; nt2++) {
            uint32_t r0, r1, r2, r3;
            ldsm_x4(r0, r1, r2, r3, slab + (boff + nt2*16u*KPAD_H)*2);
            b[0][2*nt2][0] = r0; b[0][2*nt2+1][0] = r1;
            b[0][2*nt2][1] = r2; b[0][2*nt2+1][1] = r3;
        }

        #pragma unroll
        for (int k16 = 0; k16 < BK/16; k16++) {
            int cur = k16 & 1, nxt = cur ^ 1;
            if (k16 + 1 < BK/16) {
                uint32_t kk = (uint32_t)((k16 + 1)*16)*2;
                ldsm_x4(a[nxt][0][0], a[nxt][0][1], a[nxt][0][2], a[nxt][0][3],
                        slab + aoff0*2 + kk);
                ldsm_x4(a[nxt][1][0], a[nxt][1][1], a[nxt][1][2], a[nxt][1][3],
                        slab + aoff1*2 + kk);
                #pragma unroll
                for (int nt2 = 0; nt2 < 4; nt2++) {
                    uint32_t r0, r1, r2, r3;
                    ldsm_x4(r0, r1, r2, r3, slab + (boff + nt2*16u*KPAD_H)*2 + kk);
                    b[nxt][2*nt2][0] = r0; b[nxt][2*nt2+1][0] = r1;
                    b[nxt][2*nt2][1] = r2; b[nxt][2*nt2+1][1] = r3;
                }
            }
            #pragma unroll
            for (int mt = 0; mt < 2; mt++)
                #pragma unroll
                for (int nt = 0; nt < 8; nt++)
                    mma_f16_16x8x16(acc[mt][nt][0], acc[mt][nt][1], acc[mt][nt][2], acc[mt][nt][3],
                                    a[cur][mt][0], a[cur][mt][1], a[cur][mt][2], a[cur][mt][3],
                                    b[cur][nt][0], b[cur][nt][1]);
        }
    }

    int rowa = m0 + wm*32 + lq;
    int colb = n0 + wn*64 + 2*lr;
    #pragma unroll
    for (int mt = 0; mt < 2; mt++) {
        #pragma unroll
        for (int nt = 0; nt < 8; nt++) {
            float v0 = acc[mt][nt][0], v1 = acc[mt][nt][1];
            float v2 = acc[mt][nt][2], v3 = acc[mt][nt][3];
            if (bias) {
                float b0 = bias[colb + nt*8], b1 = bias[colb + nt*8 + 1];
                v0 += b0; v1 += b1; v2 += b0; v3 += b1;
            }
            if (flags & 1) {
                v0 = fmaxf(v0, 0.f); v1 = fmaxf(v1, 0.f);
                v2 = fmaxf(v2, 0.f); v3 = fmaxf(v3, 0.f);
            }
            if (flags & 4) {
                __half* Ch = (__half*)Cv + (size_t)z*sC;
                __half2 h0 = __floats2half2_rn(v0, v1);
                __half2 h1 = __floats2half2_rn(v2, v3);
                *(__half2*)(Ch + (size_t)(rowa + mt*16)*ldc + colb + nt*8) = h0;
                *(__half2*)(Ch + (size_t)(rowa + mt*16 + 8)*ldc + colb + nt*8) = h1;
            } else {
                float* Cf = (float*)Cv + (size_t)z*sC;
                float2 w0; w0.x = v0; w0.y = v1;
                float2 w1; w1.x = v2; w1.y = v3;
                *(float2*)(Cf + (size_t)(rowa + mt*16)*ldc + colb + nt*8) = w0;
                *(float2*)(Cf + (size_t)(rowa + mt*16 + 8)*ldc + colb + nt*8) = w1;
            }
        }
    }
}

// ---------------- adp = softmax(relu(nv1 @ nv2), axis=1) ----------------
__global__ void adp_kernel(const float* __restrict__ nv1, const float* __restrict__ nv2)
{
    int row = blockIdx.x;
    int tid = threadIdx.x;
    __shared__ float v1[10];
    __shared__ float red[256];
    if (tid < 10) v1[tid] = nv1[row*10 + tid];
    __syncthreads();
    float vals[8];
    float mx = -1e30f;
    #pragma unroll
    for (int j = 0; j < 8; j++) {
        int col = tid + j*256;
        float s = 0.f;
        #pragma unroll
        for (int k = 0; k < 10; k++) s += v1[k]*nv2[k*NV + col];
        s = fmaxf(s, 0.f);
        vals[j] = s;
        mx = fmaxf(mx, s);
    }
    red[tid] = mx; __syncthreads();
    for (int s2 = 128; s2 > 0; s2 >>= 1) {
        if (tid < s2) red[tid] = fmaxf(red[tid], red[tid+s2]);
        __syncthreads();
    }
    mx = red[0];
    __syncthreads();
    float sum = 0.f;
    #pragma unroll
    for (int j = 0; j < 8; j++) { vals[j] = expf(vals[j] - mx); sum += vals[j]; }
    red[tid] = sum; __syncthreads();
    for (int s2 = 128; s2 > 0; s2 >>= 1) {
        if (tid < s2) red[tid] += red[tid+s2];
        __syncthreads();
    }
    float inv = 1.f/red[0];
    #pragma unroll
    for (int j = 0; j < 8; j++) g_adp[row*NV + tid + j*256] = vals[j]*inv;
}

// ---------------- build fp16 transposed supports ----------------
__global__ void bt_kernel(const float* __restrict__ A)
{
    __shared__ float tile[32][33];
    int z = blockIdx.z;
    const float* S = (z < 2) ? (A + (size_t)z*NN) : g_adp;
    int r0 = blockIdx.y*32, c0 = blockIdx.x*32;
    int x = threadIdx.x & 31, y = threadIdx.x >> 5;
    #pragma unroll
    for (int i = 0; i < 32; i += 8)
        tile[y+i][x] = S[(size_t)(r0 + y + i)*NV + c0 + x];
    __syncthreads();
    #pragma unroll
    for (int i = 0; i < 32; i += 8)
        g_bt[((size_t)z*NV + c0 + y + i)*NV + r0 + x] = __float2half(tile[x][y+i]);
}

// ---------------- one-time gcn weight transpose ----------------
__global__ void gw_prep(const float* __restrict__ gw)
{
    int idx = blockIdx.x*256 + threadIdx.x;
    int l  = idx / (224*32);
    int r  = idx % (224*32);
    int gc = r >> 5, q = r & 31;
    int og2 = q >> 3, j = q & 7;
    g_wgt[idx] = gw[l*NRC*224 + (og2 + j*4)*224 + gc];
}

// ---------------- one-time skip weight stack + bias sum ----------------
__global__ void wsk_prep(const float* __restrict__ sw, const float* __restrict__ sb)
{
    int idx = blockIdx.x*256 + threadIdx.x;
    int j = idx >> 8, k = idx & 255;
    int l = k >> 5, c = k & 31;
    g_wsk[idx] = __float2half(sw[(l*NSC + j)*NRC + c]);
    if (idx < NSC) {
        float s = 0.f;
        #pragma unroll
        for (int ll = 0; ll < NLAY; ll++) s += sb[ll*NSC + idx];
        g_bsk[idx] = s;
    }
}

// ---------------- one-time gated weight pack ----------------
__global__ void wf_prep(const float* __restrict__ fw, const float* __restrict__ gw)
{
    int idx = blockIdx.x*256 + threadIdx.x;
    int l = idx >> 12;
    int rem = idx & 4095;
    int q = rem >> 6, k = rem & 63;
    int o = q >> 1, isg = q & 1;
    int c = k >> 1, tap = k & 1;
    const float* W = isg ? gw : fw;
    g_wf[idx] = __float2half(W[((l*NRC + o)*NRC + c)*2 + tap]);
}

// ---------------- pad + start 1x1 conv ----------------
__global__ void start_kernel(const float* __restrict__ x,
                             const float* __restrict__ sw, const float* __restrict__ sb)
{
    int v = blockIdx.x*256 + threadIdx.x;
    int t = blockIdx.y, b = blockIdx.z;
    float in0 = 0.f, in1 = 0.f;
    if (t > 0) {
        in0 = x[((b*2+0)*NV + v)*12 + (t-1)];
        in1 = x[((b*2+1)*NV + v)*12 + (t-1)];
    }
    #pragma unroll
    for (int o = 0; o < NRC; o++) {
        g_xa[((b*NRC+o)*13 + t)*NV + v] = sb[o] + sw[o*2]*in0 + sw[o*2+1]*in1;
    }
}

// ---------------- gated dilated conv via HMMA ----------------
#define GPAD 72
__global__ void __launch_bounds__(256) gated_mma(
    const float* __restrict__ fb, const float* __restrict__ gb,
    int layer, int Tin, int d, int parity)
{
    __shared__ __half Xs[128*GPAD];
    __shared__ __half Ws[64*GPAD];
    __shared__ __half Os[32*136];
    __shared__ float sfb[NRC], sgb[NRC];

    const float* xin = parity ? g_xb : g_xa;
    int Tout = Tin - d;
    int v0 = blockIdx.x*128;
    int t = blockIdx.y, b = blockIdx.z;
    int tid = threadIdx.x, wid = tid >> 5, lane = tid & 31;
    int lq = lane >> 2, lr = lane & 3;
    int lane15 = lane & 15, laneh = lane >> 4;

    const __half* wsrc = g_wf + layer*64*64;
    for (int i = tid; i < 64*32; i += 256) {
        int row = i >> 5, col2 = (i & 31)*2;
        *(uint32_t*)&Ws[row*GPAD + col2] = *(const uint32_t*)&wsrc[row*64 + col2];
    }
    if (tid < NRC) {
        sfb[tid] = fb[layer*NRC + tid];
        sgb[tid] = gb[layer*NRC + tid];
    }
    {
        int v = tid & 127;
        #pragma unroll
        for (int i = 0; i < 32; i++) {
            int r = i*2 + (tid >> 7);
            int c = r >> 1, tap = r & 1;
            float val = xin[((b*NRC + c)*Tin + t + tap*d)*NV + v0 + v];
            Xs[v*GPAD + r] = __float2half(val);
        }
    }
    __syncthreads();

    uint32_t sx = smem_u32(Xs), sw_ = smem_u32(Ws);
    float acc[8][4];
    #pragma unroll
    for (int nt = 0; nt < 8; nt++)
        #pragma unroll
        for (int k = 0; k < 4; k++) acc[nt][k] = 0.f;

    uint32_t axa = sx + (uint32_t)((wid*16 + lane15)*GPAD + 8*laneh)*2;
    uint32_t bxa = sw_ + (uint32_t)(lane15*GPAD + 8*laneh)*2;

    #pragma unroll
    for (int k16 = 0; k16 < 4; k16++) {
        uint32_t kk = (uint32_t)(k16*16)*2;
        uint32_t a0, a1, a2, a3;
        ldsm_x4(a0, a1, a2, a3, axa + kk);
        uint32_t bfr[8][2];
        #pragma unroll
        for (int nt2 = 0; nt2 < 4; nt2++) {
            uint32_t r0, r1, r2, r3;
            ldsm_x4(r0, r1, r2, r3, bxa + (uint32_t)(nt2*16*GPAD)*2 + kk);
            bfr[2*nt2][0] = r0; bfr[2*nt2+1][0] = r1;
            bfr[2*nt2][1] = r2; bfr[2*nt2+1][1] = r3;
        }
        #pragma unroll
        for (int nt = 0; nt < 8; nt++)
            mma_f16_16x8x16(acc[nt][0], acc[nt][1], acc[nt][2], acc[nt][3],
                            a0, a1, a2, a3, bfr[nt][0], bfr[nt][1]);
    }

    #pragma unroll
    for (int nt = 0; nt < 8; nt++) {
        int o = nt*4 + lr;
        float fbv = sfb[o], gbv = sgb[o];
        float f0 = tanh_fast(acc[nt][0] + fbv);
        float g0 = 0.5f*tanh_fast(0.5f*(acc[nt][1] + gbv)) + 0.5f;
        float f1 = tanh_fast(acc[nt][2] + fbv);
        float g1 = 0.5f*tanh_fast(0.5f*(acc[nt][3] + gbv)) + 0.5f;
        Os[o*136 + wid*16 + lq]     = __float2half(f0*g0);
        Os[o*136 + wid*16 + lq + 8] = __float2half(f1*g1);
    }
    __syncthreads();

    #pragma unroll
    for (int i = 0; i < 2; i++) {
        int idx = tid + i*256;
        int row = idx >> 4, ch = idx & 15;
        uint4 val = *(const uint4*)&Os[row*136 + ch*8];
        *(uint4*)&g_gx[((size_t)(b*NRC + row)*Tout + t)*NV + v0 + ch*8] = val;
    }
    if (t == Tout - 1) {
        int v = tid >> 1, oh = tid & 1;
        __half hb[16];
        #pragma unroll
        for (int i = 0; i < 16; i++) hb[i] = Os[(oh*16 + i)*136 + v];
        uint4* dst = (uint4*)(g_gxl + ((size_t)b*NV + v0 + v)*NSC + layer*NRC + oh*16);
        const uint4* src = (const uint4*)hb;
        dst[0] = src[0]; dst[1] = src[1];
    }
}

// ---------------- gcn 1x1 conv + bias + residual + BN ----------------
__global__ __launch_bounds__(256) void gcn_kernel(
    const float* __restrict__ gb,
    const float* __restrict__ bng, const float* __restrict__ bnb,
    const float* __restrict__ bnm, const float* __restrict__ bnv,
    int layer, int Tin, int d, int parity)
{
    int Tout = Tin - d;
    const float* xin  = parity ? g_xb : g_xa;
    float*       xout = parity ? g_xa : g_xb;

    __shared__ float ws[224*32];
    __shared__ float hs[NRC][64];
    __shared__ float s_inv[NRC], s_beta[NRC], s_mean[NRC], s_gb[NRC];

    const float* wsrc = g_wgt + layer*224*32;
    for (int i = threadIdx.x; i < 224*32; i += 256) ws[i] = wsrc[i];
    if (threadIdx.x < NRC) {
        int o = threadIdx.x;
        s_inv [o] = bng[layer*NRC+o]*rsqrtf(bnv[layer*NRC+o] + 1e-5f);
        s_beta[o] = bnb[layer*NRC+o];
        s_mean[o] = bnm[layer*NRC+o];
        s_gb  [o] = gb [layer*NRC+o];
    }

    int vi = threadIdx.x & 63;
    int og = threadIdx.x >> 6;
    int v0 = blockIdx.x*64;
    int t = blockIdx.y, b = blockIdx.z;

    float acc[8];
    #pragma unroll
    for (int j = 0; j < 8; j++) acc[j] = 0.f;

    for (int g = 0; g < 7; g++) {
        const __half* H = (g == 0) ? g_gx : (g_H + (size_t)(g-1)*HBUF);
        __syncthreads();
        for (int i = threadIdx.x; i < NRC*64; i += 256) {
            int c = i >> 6, vv = i & 63;
            hs[c][vv] = __half2float(H[((b*NRC+c)*Tout + t)*NV + v0 + vv]);
        }
        __syncthreads();
        #pragma unroll
        for (int c = 0; c < 32; c++) {
            float hv = hs[c][vi];
            const float4* wp = (const float4*)&ws[(g*32 + c)*32 + og*8];
            float4 wa = wp[0], wb = wp[1];
            acc[0] += wa.x*hv; acc[1] += wa.y*hv; acc[2] += wa.z*hv; acc[3] += wa.w*hv;
            acc[4] += wb.x*hv; acc[5] += wb.y*hv; acc[6] += wb.z*hv; acc[7] += wb.w*hv;
        }
    }

    #pragma unroll
    for (int j = 0; j < 8; j++) {
        int o = og + j*4;
        float val = acc[j] + s_gb[o]
                  + xin[((b*NRC+o)*Tin + (t + d))*NV + v0 + vi];
        val = (val - s_mean[o])*s_inv[o] + s_beta[o];
        xout[((b*NRC+o)*Tout + t)*NV + v0 + vi] = val;
    }
}

// ---------------- fp16 end1 weights ----------------
__global__ void w1r_kernel(const float* __restrict__ e1w)
{
    int idx = blockIdx.x*256 + threadIdx.x;
    g_w1r[idx] = __float2half(e1w[idx]);
}

// ---------------- end2 ----------------
__global__ __launch_bounds__(256) void end2_kernel(
    const float* __restrict__ e2w, const float* __restrict__ e2b, float* __restrict__ out)
{
    __shared__ float w[NOUT*NEC];
    __shared__ float sb[NOUT];
    for (int i = threadIdx.x; i < NOUT*NEC; i += 256) w[i] = e2w[i];
    if (threadIdx.x < NOUT) sb[threadIdx.x] = e2b[threadIdx.x];
    __syncthreads();

    int warp = threadIdx.x >> 5, lane = threadIdx.x & 31;
    int row = blockIdx.x*8 + warp;
    const float* e1r = g_e1 + (size_t)row*NEC;
    float r[16];
    #pragma unroll
    for (int k = 0; k < 16; k++) r[k] = e1r[lane + k*32];
    int b = row >> 11, v = row & (NV-1);
    #pragma unroll
    for (int o = 0; o < NOUT; o++) {
        float s = 0.f;
        #pragma unroll
        for (int k = 0; k < 16; k++) s += r[k]*w[o*NEC + lane + k*32];
        #pragma unroll
        for (int off = 16; off; off >>= 1) s += __shfl_xor_sync(0xffffffffu, s, off);
        if (lane == 0) out[((size_t)b*NOUT + o)*NV + v] = s + sb[o];
    }
}

// ---------------- launch ----------------
extern "C" void kernel_launch(void* const* d_in, const int* in_sizes, int n_in,
                              void* d_out, int out_size)
{
    (void)in_sizes; (void)n_in; (void)out_size;
    const float* x    = (const float*)d_in[0];
    const float* A    = (const float*)d_in[1];
    const float* nv1  = (const float*)d_in[2];
    const float* nv2  = (const float*)d_in[3];
    const float* fw   = (const float*)d_in[4];
    const float* fb   = (const float*)d_in[5];
    const float* gw   = (const float*)d_in[6];
    const float* gb   = (const float*)d_in[7];
    const float* sw   = (const float*)d_in[8];
    const float* sb   = (const float*)d_in[9];
    const float* gcnw = (const float*)d_in[10];
    const float* gcnb = (const float*)d_in[11];
    const float* bng  = (const float*)d_in[12];
    const float* bnb  = (const float*)d_in[13];
    const float* bnm  = (const float*)d_in[14];
    const float* bnv  = (const float*)d_in[15];
    const float* stw  = (const float*)d_in[16];
    const float* stb  = (const float*)d_in[17];
    const float* e1w  = (const float*)d_in[18];
    const float* e1b  = (const float*)d_in[19];
    const float* e2w  = (const float*)d_in[20];
    const float* e2b  = (const float*)d_in[21];

    __half *p_gx, *p_H, *p_skt, *p_w1r, *p_bt, *p_gxl, *p_wsk;
    float  *p_e1, *p_bsk;
    cudaGetSymbolAddress((void**)&p_gx,   g_gx);
    cudaGetSymbolAddress((void**)&p_H,    g_H);
    cudaGetSymbolAddress((void**)&p_skt,  g_skt);
    cudaGetSymbolAddress((void**)&p_e1,   g_e1);
    cudaGetSymbolAddress((void**)&p_w1r,  g_w1r);
    cudaGetSymbolAddress((void**)&p_bt,   g_bt);
    cudaGetSymbolAddress((void**)&p_gxl,  g_gxl);
    cudaGetSymbolAddress((void**)&p_wsk,  g_wsk);
    cudaGetSymbolAddress((void**)&p_bsk,  g_bsk);

    cudaFuncSetAttribute(mma_gemm, cudaFuncAttributeMaxDynamicSharedMemorySize, GSMEM);

    adp_kernel<<<NV, 256>>>(nv1, nv2);
    bt_kernel<<<dim3(NV/32, NV/32, 3), 256>>>(A);
    gw_prep<<<(NLAY*224*32)/256, 256>>>(gcnw);
    wsk_prep<<<(NSC*NSC)/256, 256>>>(sw, sb);
    wf_prep<<<(NLAY*64*64)/256, 256>>>(fw, gw);
    start_kernel<<<dim3(NV/256, 13, NB), 256>>>(x, stw, stb);

    const int dil[NLAY] = {1,2,1,2,1,2,1,2};
    int Tin = 13, parity = 0;
    for (int i = 0; i < NLAY; i++) {
        int d = dil[i], Tout = Tin - d;
        gated_mma<<<dim3(NV/128, Tout, NB), 256>>>(fb, gb, i, Tin, d, parity);

        if (i < NLAY-1) {   // last layer's gcn output is dead code
            int M = NB*NRC*Tout;
            // hop 1: gx @ A_z -> H0, H2, H4
            mma_gemm<<<dim3(NV/BN, M/BM, 3), NTHR, GSMEM>>>(
                p_gx, p_bt, p_H,
                0L, (long)NN, 2L*HBUF,
                NV, NV, NV, NV/BK, nullptr, 4);
            // hop 2: H{0,2,4} @ A_z -> H1, H3, H5
            mma_gemm<<<dim3(NV/BN, M/BM, 3), NTHR, GSMEM>>>(
                p_H, p_bt, p_H + HBUF,
                2L*HBUF, (long)NN, 2L*HBUF,
                NV, NV, NV, NV/BK, nullptr, 4);
            gcn_kernel<<<dim3(NV/64, Tout, NB), 256>>>(gcnb, bng, bnb, bnm, bnv,
                                                       i, Tin, d, parity);
        }
        parity ^= 1;
        Tin = Tout;
    }

    // skt[bv][j] = relu(gxl[bv][:] . wsk[j][:] + bsk[j])  (fp16 out)
    mma_gemm<<<dim3(NSC/BN, (NB*NV)/BM, 1), NTHR, GSMEM>>>(
        p_gxl, p_wsk, p_skt,
        0L, 0L, 0L,
        NSC, NSC, NSC, NSC/BK, p_bsk, 1|4);
    w1r_kernel<<<(NEC*NSC)/256, 256>>>(e1w);
    // E1 = relu(skt @ e1w^T + b1)
    mma_gemm<<<dim3(NEC/BN, (NB*NV)/BM, 1), NTHR, GSMEM>>>(
        p_skt, p_w1r, p_e1,
        0L, 0L, 0L,
        NSC, NSC, NEC, NSC/BK, e1b, 1);
    end2_kernel<<<(NB*NV)/8, 256>>>(e2w, e2b, (float*)d_out);
}

// round 14
// speedup vs baseline: 1.0980x; 1.0980x over previous
#include <cuda_runtime.h>
#include <cuda_fp16.h>
#include <math.h>
#include <stdint.h>

// ---------------- problem constants ----------------
#define NB   16
#define NV   2048
#define NRC  32
#define NSC  256
#define NEC  512
#define NOUT 12
#define NLAY 8
#define NN   (NV*NV)
#define XBUF (NB*NRC*13*NV)
#define HBUF (NB*NRC*12*NV)

// ---------------- device scratch ----------------
__device__ float  g_adp [NN];
__device__ __half g_bt  [3*NN];          // fp16 transposed supports [z][n][k]
__device__ float  g_xa  [XBUF];
__device__ float  g_xb  [XBUF];
__device__ __half g_gx  [HBUF];
__device__ __half g_H   [6*HBUF];
__device__ __half g_gxl [NB*NV*NSC];     // last-timestep gated outs [bv][l*32+c]
__device__ __half g_wsk [NSC*NSC];       // stacked skip weights [j][l*32+c]
__device__ float  g_bsk [NSC];           // summed skip bias
__device__ __half g_skt [NB*NV*NSC];     // relu'd skip, [bv][j] fp16
__device__ float  g_e1  [NB*NV*NEC];
__device__ __half g_w1r [NEC*NSC];       // fp16 e1w, already [n][k]
__device__ __half g_wg  [NLAY*NRC*224];  // gcn weights fp16 [l][o][k]
__device__ __half g_wf  [NLAY*64*64];    // gated weights [l][q=2o+isg][k=2c+tap]

// ---------------- helpers ----------------
__device__ __forceinline__ float tanh_fast(float x) {
    float y; asm("tanh.approx.f32 %0, %1;" : "=f"(y) : "f"(x));
    return y;
}
__device__ __forceinline__ uint32_t smem_u32(const void* p) {
    uint32_t a;
    asm("{ .reg .u64 t; cvta.to.shared.u64 t, %1; cvt.u32.u64 %0, t; }" : "=r"(a) : "l"(p));
    return a;
}
__device__ __forceinline__ void cp_async16(uint32_t dst, const void* src) {
    asm volatile("cp.async.cg.shared.global [%0], [%1], 16;" :: "r"(dst), "l"(src));
}
#define CP_COMMIT() asm volatile("cp.async.commit_group;" ::: "memory")

__device__ __forceinline__ void mma_f16_16x8x16(
    float& d0, float& d1, float& d2, float& d3,
    uint32_t a0, uint32_t a1, uint32_t a2, uint32_t a3,
    uint32_t b0, uint32_t b1)
{
    asm volatile(
        "mma.sync.aligned.m16n8k16.row.col.f32.f16.f16.f32 "
        "{%0,%1,%2,%3}, {%4,%5,%6,%7}, {%8,%9}, {%0,%1,%2,%3};"
        : "+f"(d0), "+f"(d1), "+f"(d2), "+f"(d3)
        : "r"(a0), "r"(a1), "r"(a2), "r"(a3), "r"(b0), "r"(b1));
}
__device__ __forceinline__ void ldsm_x4(
    uint32_t& r0, uint32_t& r1, uint32_t& r2, uint32_t& r3, uint32_t addr)
{
    asm volatile("ldmatrix.sync.aligned.m8n8.x4.shared.b16 {%0,%1,%2,%3}, [%4];"
        : "=r"(r0), "=r"(r1), "=r"(r2), "=r"(r3) : "r"(addr));
}

// ---------------- fp16 HMMA GEMM (R11 config): C[M,N] = X[M,K] @ B[N,K]^T ----------------
// CTA tile 128x128, BK=64, 256 thr = 8 warps (4m x 2n), warp tile 32x64, 3-stage
// cp.async, register double-buffered ldmatrix fragments. flags: bit0 relu, bit2 fp16 out.
#define BM 128
#define BN 128
#define BK 64
#define KPAD_H 72
#define STG_H (BM*KPAD_H)
#define NSTAGE 3
#define GSMEM (NSTAGE*2*STG_H*2)

__global__ void __launch_bounds__(256) mma_gemm(
    const __half* __restrict__ X, const __half* __restrict__ B, void* __restrict__ Cv,
    long sX, long sB, long sC,
    int lda, int ldb, int ldc, int nkt,
    const float* __restrict__ bias, int flags)
{
    extern __shared__ __half sm[];

    int z = blockIdx.z;
    X += (size_t)z*sX;
    B += (size_t)z*sB;
    int m0 = blockIdx.y*BM, n0 = blockIdx.x*BN;

    int tid = threadIdx.x, wid = tid >> 5, lane = tid & 31;
    int wm = wid & 3, wn = wid >> 2;
    int lq = lane >> 2, lr = lane & 3;
    int lane15 = lane & 15, laneh = lane >> 4;

    uint32_t sbase = smem_u32(sm);

    auto load_stage = [&](int s, int k0) {
        uint32_t da = sbase + (uint32_t)(s*2*STG_H)*2;
        uint32_t db = da + (uint32_t)STG_H*2;
        const __half* xs = X + (size_t)m0*lda + k0;
        const __half* bs = B + (size_t)n0*ldb + k0;
        #pragma unroll
        for (int i = 0; i < 4; i++) {
            int l = tid + i*256;
            int row = l >> 3, seg = l & 7;
            uint32_t off = (uint32_t)(row*KPAD_H + seg*8)*2;
            cp_async16(da + off, xs + (size_t)row*lda + seg*8);
            cp_async16(db + off, bs + (size_t)row*ldb + seg*8);
        }
    };

    float acc[2][8][4];
    #pragma unroll
    for (int mt = 0; mt < 2; mt++)
        #pragma unroll
        for (int nt = 0; nt < 8; nt++)
            #pragma unroll
            for (int k = 0; k < 4; k++) acc[mt][nt][k] = 0.f;

    load_stage(0, 0);  CP_COMMIT();
    if (nkt > 1) load_stage(1, BK);
    CP_COMMIT();

    uint32_t aoff0 = (uint32_t)((wm*32 + lane15)*KPAD_H + 8*laneh);
    uint32_t aoff1 = aoff0 + 16u*KPAD_H;
    uint32_t boff  = (uint32_t)(STG_H + (wn*64 + lane15)*KPAD_H + 8*laneh);

    for (int kt = 0; kt < nkt; kt++) {
        asm volatile("cp.async.wait_group 1;" ::: "memory");
        __syncthreads();

        if (kt + 2 < nkt) load_stage((kt+2) % NSTAGE, (kt+2)*BK);
        CP_COMMIT();

        uint32_t slab = sbase + (uint32_t)((kt % NSTAGE)*2*STG_H)*2;

        uint32_t a[2][2][4], b[2][8][2];
        ldsm_x4(a[0][0][0], a[0][0][1], a[0][0][2], a[0][0][3], slab + aoff0*2);
        ldsm_x4(a[0][1][0], a[0][1][1], a[0][1][2], a[0][1][3], slab + aoff1*2);
        #pragma unroll
        for (int nt2 = 0; nt2 < 4; nt2++) {
            uint32_t r0, r1, r2, r3;
            ldsm_x4(r0, r1, r2, r3, slab + (boff + nt2*16u*KPAD_H)*2);
            b[0][2*nt2][0] = r0; b[0][2*nt2+1][0] = r1;
            b[0][2*nt2][1] = r2; b[0][2*nt2+1][1] = r3;
        }

        #pragma unroll
        for (int k16 = 0; k16 < BK/16; k16++) {
            int cur = k16 & 1, nxt = cur ^ 1;
            if (k16 + 1 < BK/16) {
                uint32_t kk = (uint32_t)((k16 + 1)*16)*2;
                ldsm_x4(a[nxt][0][0], a[nxt][0][1], a[nxt][0][2], a[nxt][0][3],
                        slab + aoff0*2 + kk);
                ldsm_x4(a[nxt][1][0], a[nxt][1][1], a[nxt][1][2], a[nxt][1][3],
                        slab + aoff1*2 + kk);
                #pragma unroll
                for (int nt2 = 0; nt2 < 4; nt2++) {
                    uint32_t r0, r1, r2, r3;
                    ldsm_x4(r0, r1, r2, r3, slab + (boff + nt2*16u*KPAD_H)*2 + kk);
                    b[nxt][2*nt2][0] = r0; b[nxt][2*nt2+1][0] = r1;
                    b[nxt][2*nt2][1] = r2; b[nxt][2*nt2+1][1] = r3;
                }
            }
            #pragma unroll
            for (int mt = 0; mt < 2; mt++)
                #pragma unroll
                for (int nt = 0; nt < 8; nt++)
                    mma_f16_16x8x16(acc[mt][nt][0], acc[mt][nt][1], acc[mt][nt][2], acc[mt][nt][3],
                                    a[cur][mt][0], a[cur][mt][1], a[cur][mt][2], a[cur][mt][3],
                                    b[cur][nt][0], b[cur][nt][1]);
        }
    }

    int rowa = m0 + wm*32 + lq;
    int colb = n0 + wn*64 + 2*lr;
    #pragma unroll
    for (int mt = 0; mt < 2; mt++) {
        #pragma unroll
        for (int nt = 0; nt < 8; nt++) {
            float v0 = acc[mt][nt][0], v1 = acc[mt][nt][1];
            float v2 = acc[mt][nt][2], v3 = acc[mt][nt][3];
            if (bias) {
                float b0 = bias[colb + nt*8], b1 = bias[colb + nt*8 + 1];
                v0 += b0; v1 += b1; v2 += b0; v3 += b1;
            }
            if (flags & 1) {
                v0 = fmaxf(v0, 0.f); v1 = fmaxf(v1, 0.f);
                v2 = fmaxf(v2, 0.f); v3 = fmaxf(v3, 0.f);
            }
            if (flags & 4) {
                __half* Ch = (__half*)Cv + (size_t)z*sC;
                __half2 h0 = __floats2half2_rn(v0, v1);
                __half2 h1 = __floats2half2_rn(v2, v3);
                *(__half2*)(Ch + (size_t)(rowa + mt*16)*ldc + colb + nt*8) = h0;
                *(__half2*)(Ch + (size_t)(rowa + mt*16 + 8)*ldc + colb + nt*8) = h1;
            } else {
                float* Cf = (float*)Cv + (size_t)z*sC;
                float2 w0; w0.x = v0; w0.y = v1;
                float2 w1; w1.x = v2; w1.y = v3;
                *(float2*)(Cf + (size_t)(rowa + mt*16)*ldc + colb + nt*8) = w0;
                *(float2*)(Cf + (size_t)(rowa + mt*16 + 8)*ldc + colb + nt*8) = w1;
            }
        }
    }
}

// ---------------- adp = softmax(relu(nv1 @ nv2), axis=1) ----------------
__global__ void adp_kernel(const float* __restrict__ nv1, const float* __restrict__ nv2)
{
    int row = blockIdx.x;
    int tid = threadIdx.x;
    __shared__ float v1[10];
    __shared__ float red[256];
    if (tid < 10) v1[tid] = nv1[row*10 + tid];
    __syncthreads();
    float vals[8];
    float mx = -1e30f;
    #pragma unroll
    for (int j = 0; j < 8; j++) {
        int col = tid + j*256;
        float s = 0.f;
        #pragma unroll
        for (int k = 0; k < 10; k++) s += v1[k]*nv2[k*NV + col];
        s = fmaxf(s, 0.f);
        vals[j] = s;
        mx = fmaxf(mx, s);
    }
    red[tid] = mx; __syncthreads();
    for (int s2 = 128; s2 > 0; s2 >>= 1) {
        if (tid < s2) red[tid] = fmaxf(red[tid], red[tid+s2]);
        __syncthreads();
    }
    mx = red[0];
    __syncthreads();
    float sum = 0.f;
    #pragma unroll
    for (int j = 0; j < 8; j++) { vals[j] = expf(vals[j] - mx); sum += vals[j]; }
    red[tid] = sum; __syncthreads();
    for (int s2 = 128; s2 > 0; s2 >>= 1) {
        if (tid < s2) red[tid] += red[tid+s2];
        __syncthreads();
    }
    float inv = 1.f/red[0];
    #pragma unroll
    for (int j = 0; j < 8; j++) g_adp[row*NV + tid + j*256] = vals[j]*inv;
}

// ---------------- build fp16 transposed supports ----------------
__global__ void bt_kernel(const float* __restrict__ A)
{
    __shared__ float tile[32][33];
    int z = blockIdx.z;
    const float* S = (z < 2) ? (A + (size_t)z*NN) : g_adp;
    int r0 = blockIdx.y*32, c0 = blockIdx.x*32;
    int x = threadIdx.x & 31, y = threadIdx.x >> 5;
    #pragma unroll
    for (int i = 0; i < 32; i += 8)
        tile[y+i][x] = S[(size_t)(r0 + y + i)*NV + c0 + x];
    __syncthreads();
    #pragma unroll
    for (int i = 0; i < 32; i += 8)
        g_bt[((size_t)z*NV + c0 + y + i)*NV + r0 + x] = __float2half(tile[x][y+i]);
}

// ---------------- one-time gcn weight fp16 convert ----------------
__global__ void gw_prep(const float* __restrict__ gw)
{
    int idx = blockIdx.x*256 + threadIdx.x;   // NLAY*32*224 = 57344
    g_wg[idx] = __float2half(gw[idx]);
}

// ---------------- one-time skip weight stack + bias sum ----------------
__global__ void wsk_prep(const float* __restrict__ sw, const float* __restrict__ sb)
{
    int idx = blockIdx.x*256 + threadIdx.x;
    int j = idx >> 8, k = idx & 255;
    int l = k >> 5, c = k & 31;
    g_wsk[idx] = __float2half(sw[(l*NSC + j)*NRC + c]);
    if (idx < NSC) {
        float s = 0.f;
        #pragma unroll
        for (int ll = 0; ll < NLAY; ll++) s += sb[ll*NSC + idx];
        g_bsk[idx] = s;
    }
}

// ---------------- one-time gated weight pack ----------------
__global__ void wf_prep(const float* __restrict__ fw, const float* __restrict__ gw)
{
    int idx = blockIdx.x*256 + threadIdx.x;
    int l = idx >> 12;
    int rem = idx & 4095;
    int q = rem >> 6, k = rem & 63;
    int o = q >> 1, isg = q & 1;
    int c = k >> 1, tap = k & 1;
    const float* W = isg ? gw : fw;
    g_wf[idx] = __float2half(W[((l*NRC + o)*NRC + c)*2 + tap]);
}

// ---------------- pad + start 1x1 conv ----------------
__global__ void start_kernel(const float* __restrict__ x,
                             const float* __restrict__ sw, const float* __restrict__ sb)
{
    int v = blockIdx.x*256 + threadIdx.x;
    int t = blockIdx.y, b = blockIdx.z;
    float in0 = 0.f, in1 = 0.f;
    if (t > 0) {
        in0 = x[((b*2+0)*NV + v)*12 + (t-1)];
        in1 = x[((b*2+1)*NV + v)*12 + (t-1)];
    }
    #pragma unroll
    for (int o = 0; o < NRC; o++) {
        g_xa[((b*NRC+o)*13 + t)*NV + v] = sb[o] + sw[o*2]*in0 + sw[o*2+1]*in1;
    }
}

// ---------------- gated dilated conv via HMMA ----------------
#define GPAD 72
__global__ void __launch_bounds__(256) gated_mma(
    const float* __restrict__ fb, const float* __restrict__ gb,
    int layer, int Tin, int d, int parity)
{
    __shared__ __half Xs[128*GPAD];
    __shared__ __half Ws[64*GPAD];
    __shared__ __half Os[32*136];
    __shared__ float sfb[NRC], sgb[NRC];

    const float* xin = parity ? g_xb : g_xa;
    int Tout = Tin - d;
    int v0 = blockIdx.x*128;
    int t = blockIdx.y, b = blockIdx.z;
    int tid = threadIdx.x, wid = tid >> 5, lane = tid & 31;
    int lq = lane >> 2, lr = lane & 3;
    int lane15 = lane & 15, laneh = lane >> 4;

    const __half* wsrc = g_wf + layer*64*64;
    for (int i = tid; i < 64*32; i += 256) {
        int row = i >> 5, col2 = (i & 31)*2;
        *(uint32_t*)&Ws[row*GPAD + col2] = *(const uint32_t*)&wsrc[row*64 + col2];
    }
    if (tid < NRC) {
        sfb[tid] = fb[layer*NRC + tid];
        sgb[tid] = gb[layer*NRC + tid];
    }
    {
        int v = tid & 127;
        #pragma unroll
        for (int i = 0; i < 32; i++) {
            int r = i*2 + (tid >> 7);
            int c = r >> 1, tap = r & 1;
            float val = xin[((b*NRC + c)*Tin + t + tap*d)*NV + v0 + v];
            Xs[v*GPAD + r] = __float2half(val);
        }
    }
    __syncthreads();

    uint32_t sx = smem_u32(Xs), sw_ = smem_u32(Ws);
    float acc[8][4];
    #pragma unroll
    for (int nt = 0; nt < 8; nt++)
        #pragma unroll
        for (int k = 0; k < 4; k++) acc[nt][k] = 0.f;

    uint32_t axa = sx + (uint32_t)((wid*16 + lane15)*GPAD + 8*laneh)*2;
    uint32_t bxa = sw_ + (uint32_t)(lane15*GPAD + 8*laneh)*2;

    #pragma unroll
    for (int k16 = 0; k16 < 4; k16++) {
        uint32_t kk = (uint32_t)(k16*16)*2;
        uint32_t a0, a1, a2, a3;
        ldsm_x4(a0, a1, a2, a3, axa + kk);
        uint32_t bfr[8][2];
        #pragma unroll
        for (int nt2 = 0; nt2 < 4; nt2++) {
            uint32_t r0, r1, r2, r3;
            ldsm_x4(r0, r1, r2, r3, bxa + (uint32_t)(nt2*16*GPAD)*2 + kk);
            bfr[2*nt2][0] = r0; bfr[2*nt2+1][0] = r1;
            bfr[2*nt2][1] = r2; bfr[2*nt2+1][1] = r3;
        }
        #pragma unroll
        for (int nt = 0; nt < 8; nt++)
            mma_f16_16x8x16(acc[nt][0], acc[nt][1], acc[nt][2], acc[nt][3],
                            a0, a1, a2, a3, bfr[nt][0], bfr[nt][1]);
    }

    #pragma unroll
    for (int nt = 0; nt < 8; nt++) {
        int o = nt*4 + lr;
        float fbv = sfb[o], gbv = sgb[o];
        float f0 = tanh_fast(acc[nt][0] + fbv);
        float g0 = 0.5f*tanh_fast(0.5f*(acc[nt][1] + gbv)) + 0.5f;
        float f1 = tanh_fast(acc[nt][2] + fbv);
        float g1 = 0.5f*tanh_fast(0.5f*(acc[nt][3] + gbv)) + 0.5f;
        Os[o*136 + wid*16 + lq]     = __float2half(f0*g0);
        Os[o*136 + wid*16 + lq + 8] = __float2half(f1*g1);
    }
    __syncthreads();

    #pragma unroll
    for (int i = 0; i < 2; i++) {
        int idx = tid + i*256;
        int row = idx >> 4, ch = idx & 15;
        uint4 val = *(const uint4*)&Os[row*136 + ch*8];
        *(uint4*)&g_gx[((size_t)(b*NRC + row)*Tout + t)*NV + v0 + ch*8] = val;
    }
    if (t == Tout - 1) {
        int v = tid >> 1, oh = tid & 1;
        __half hb[16];
        #pragma unroll
        for (int i = 0; i < 16; i++) hb[i] = Os[(oh*16 + i)*136 + v];
        uint4* dst = (uint4*)(g_gxl + ((size_t)b*NV + v0 + v)*NSC + layer*NRC + oh*16);
        const uint4* src = (const uint4*)hb;
        dst[0] = src[0]; dst[1] = src[1];
    }
}

// ---------------- gcn via HMMA: C[128v,32o] = Xcat[128v,224k] @ W[32o,224k]^T ----------------
// Xcat stacks [gx, H0..H5]. Swizzled 512B rows (16B chunk: (c&24)|((c^v)&7)).
// Epilogue: bias + residual + BN, coalesced fp32 I/O.
#define XROW 256                           // halves per Xs row (512B)
#define WPAD 232
#define GCN_SMEM (128*XROW*2 + 32*WPAD*2 + 32*132*4 + 512)

__global__ void __launch_bounds__(256) gcn_mma(
    const float* __restrict__ gb,
    const float* __restrict__ bng, const float* __restrict__ bnb,
    const float* __restrict__ bnm, const float* __restrict__ bnv,
    int layer, int Tin, int d, int parity)
{
    extern __shared__ __half dsm[];
    __half* Xs = dsm;                                  // 128 x 256 halves
    __half* Ws = dsm + 128*XROW;                       // 32 x 232 halves
    float*  Os = (float*)(dsm + 128*XROW + 32*WPAD);   // 32 x 132 floats
    float*  cst = Os + 32*132;                         // inv, beta, mean, gb (4x32)

    int Tout = Tin - d;
    const float* xin  = parity ? g_xb : g_xa;
    float*       xout = parity ? g_xa : g_xb;
    int v0 = blockIdx.x*128;
    int t = blockIdx.y, b = blockIdx.z;
    int tid = threadIdx.x, wid = tid >> 5, lane = tid & 31;
    int lq = lane >> 2, lr = lane & 3;
    int lane15 = lane & 15, laneh = lane >> 4;

    // stage W [32o][224k] -> Ws rows padded to 232
    const __half* wsrc = g_wg + layer*NRC*224;
    for (int i = tid; i < 32*28; i += 256) {           // 896 16B-chunks
        int o = i / 28, c = i % 28;
        *(uint4*)&Ws[o*WPAD + c*8] = *(const uint4*)&wsrc[o*224 + c*8];
    }
    if (tid < NRC) {
        cst[tid]      = bng[layer*NRC+tid]*rsqrtf(bnv[layer*NRC+tid] + 1e-5f);
        cst[32 + tid] = bnb[layer*NRC+tid];
        cst[64 + tid] = bnm[layer*NRC+tid];
        cst[96 + tid] = gb [layer*NRC+tid];
    }

    // stage Xcat: thread v = tid&127 handles chunks c = hs, hs+2, ... (hs = tid>>7)
    {
        int v = tid & 127;
        int hs = tid >> 7;
        const long TNV = (long)Tout*NV;
        const __half* bases[7];
        #pragma unroll
        for (int g = 0; g < 7; g++) {
            const __half* Hp = (g == 0) ? g_gx : (g_H + (size_t)(g-1)*HBUF);
            bases[g] = Hp + ((size_t)(b*NRC)*Tout + t)*NV + v0 + v;
        }
        #pragma unroll
        for (int i = 0; i < 14; i++) {
            int c = hs + i*2;                         // 0..27
            int g = c >> 2, cb = (c & 3)*8;
            const __half* bp = bases[g];
            __half tmp[8];
            #pragma unroll
            for (int j = 0; j < 8; j++) tmp[j] = bp[(long)(cb + j)*TNV];
            int phys = (c & 24) | ((c ^ v) & 7);
            *(uint4*)&Xs[v*XROW + phys*8] = *(const uint4*)tmp;
        }
    }
    __syncthreads();

    uint32_t sx = smem_u32(Xs), sw_ = smem_u32(Ws);
    float acc[4][4];
    #pragma unroll
    for (int nt = 0; nt < 4; nt++)
        #pragma unroll
        for (int k = 0; k < 4; k++) acc[nt][k] = 0.f;

    int ar = wid*16 + lane15;                          // A row (v)
    uint32_t bxa = sw_ + (uint32_t)(lane15*WPAD + 8*laneh)*2;

    #pragma unroll
    for (int kc = 0; kc < 14; kc++) {
        int c = 2*kc + laneh;
        int physA = (c & 24) | ((c ^ ar) & 7);
        uint32_t a0, a1, a2, a3;
        ldsm_x4(a0, a1, a2, a3, sx + (uint32_t)(ar*XROW + physA*8)*2);
        uint32_t bfr[4][2];
        #pragma unroll
        for (int nt2 = 0; nt2 < 2; nt2++) {
            uint32_t r0, r1, r2, r3;
            ldsm_x4(r0, r1, r2, r3, bxa + (uint32_t)(nt2*16*WPAD + kc*16)*2);
            bfr[2*nt2][0] = r0; bfr[2*nt2+1][0] = r1;
            bfr[2*nt2][1] = r2; bfr[2*nt2+1][1] = r3;
        }
        #pragma unroll
        for (int nt = 0; nt < 4; nt++)
            mma_f16_16x8x16(acc[nt][0], acc[nt][1], acc[nt][2], acc[nt][3],
                            a0, a1, a2, a3, bfr[nt][0], bfr[nt][1]);
    }

    // scatter acc -> Os[o][v] (fp32)
    #pragma unroll
    for (int nt = 0; nt < 4; nt++) {
        int o = nt*8 + 2*lr;
        int v = wid*16 + lq;
        Os[o*132 + v]           = acc[nt][0];
        Os[(o+1)*132 + v]       = acc[nt][1];
        Os[o*132 + v + 8]       = acc[nt][2];
        Os[(o+1)*132 + v + 8]   = acc[nt][3];
    }
    __syncthreads();

    // fused bias + residual + BN, coalesced
    #pragma unroll
    for (int i = 0; i < 16; i++) {
        int idx = tid + i*256;                         // 4096 = 32o x 128v
        int o = idx >> 7, v = idx & 127;
        float val = Os[o*132 + v] + cst[96 + o]
                  + xin[((size_t)(b*NRC + o)*Tin + t + d)*NV + v0 + v];
        val = (val - cst[64 + o])*cst[o] + cst[32 + o];
        xout[((size_t)(b*NRC + o)*Tout + t)*NV + v0 + v] = val;
    }
}

// ---------------- fp16 end1 weights ----------------
__global__ void w1r_kernel(const float* __restrict__ e1w)
{
    int idx = blockIdx.x*256 + threadIdx.x;
    g_w1r[idx] = __float2half(e1w[idx]);
}

// ---------------- end2 ----------------
__global__ __launch_bounds__(256) void end2_kernel(
    const float* __restrict__ e2w, const float* __restrict__ e2b, float* __restrict__ out)
{
    __shared__ float w[NOUT*NEC];
    __shared__ float sb[NOUT];
    for (int i = threadIdx.x; i < NOUT*NEC; i += 256) w[i] = e2w[i];
    if (threadIdx.x < NOUT) sb[threadIdx.x] = e2b[threadIdx.x];
    __syncthreads();

    int warp = threadIdx.x >> 5, lane = threadIdx.x & 31;
    int row = blockIdx.x*8 + warp;
    const float* e1r = g_e1 + (size_t)row*NEC;
    float r[16];
    #pragma unroll
    for (int k = 0; k < 16; k++) r[k] = e1r[lane + k*32];
    int b = row >> 11, v = row & (NV-1);
    #pragma unroll
    for (int o = 0; o < NOUT; o++) {
        float s = 0.f;
        #pragma unroll
        for (int k = 0; k < 16; k++) s += r[k]*w[o*NEC + lane + k*32];
        #pragma unroll
        for (int off = 16; off; off >>= 1) s += __shfl_xor_sync(0xffffffffu, s, off);
        if (lane == 0) out[((size_t)b*NOUT + o)*NV + v] = s + sb[o];
    }
}

// ---------------- launch ----------------
extern "C" void kernel_launch(void* const* d_in, const int* in_sizes, int n_in,
                              void* d_out, int out_size)
{
    (void)in_sizes; (void)n_in; (void)out_size;
    const float* x    = (const float*)d_in[0];
    const float* A    = (const float*)d_in[1];
    const float* nv1  = (const float*)d_in[2];
    const float* nv2  = (const float*)d_in[3];
    const float* fw   = (const float*)d_in[4];
    const float* fb   = (const float*)d_in[5];
    const float* gw   = (const float*)d_in[6];
    const float* gb   = (const float*)d_in[7];
    const float* sw   = (const float*)d_in[8];
    const float* sb   = (const float*)d_in[9];
    const float* gcnw = (const float*)d_in[10];
    const float* gcnb = (const float*)d_in[11];
    const float* bng  = (const float*)d_in[12];
    const float* bnb  = (const float*)d_in[13];
    const float* bnm  = (const float*)d_in[14];
    const float* bnv  = (const float*)d_in[15];
    const float* stw  = (const float*)d_in[16];
    const float* stb  = (const float*)d_in[17];
    const float* e1w  = (const float*)d_in[18];
    const float* e1b  = (const float*)d_in[19];
    const float* e2w  = (const float*)d_in[20];
    const float* e2b  = (const float*)d_in[21];

    __half *p_gx, *p_H, *p_skt, *p_w1r, *p_bt, *p_gxl, *p_wsk;
    float  *p_e1, *p_bsk;
    cudaGetSymbolAddress((void**)&p_gx,   g_gx);
    cudaGetSymbolAddress((void**)&p_H,    g_H);
    cudaGetSymbolAddress((void**)&p_skt,  g_skt);
    cudaGetSymbolAddress((void**)&p_e1,   g_e1);
    cudaGetSymbolAddress((void**)&p_w1r,  g_w1r);
    cudaGetSymbolAddress((void**)&p_bt,   g_bt);
    cudaGetSymbolAddress((void**)&p_gxl,  g_gxl);
    cudaGetSymbolAddress((void**)&p_wsk,  g_wsk);
    cudaGetSymbolAddress((void**)&p_bsk,  g_bsk);

    cudaFuncSetAttribute(mma_gemm, cudaFuncAttributeMaxDynamicSharedMemorySize, GSMEM);
    cudaFuncSetAttribute(gcn_mma,  cudaFuncAttributeMaxDynamicSharedMemorySize, GCN_SMEM);

    adp_kernel<<<NV, 256>>>(nv1, nv2);
    bt_kernel<<<dim3(NV/32, NV/32, 3), 256>>>(A);
    gw_prep<<<(NLAY*NRC*224)/256, 256>>>(gcnw);
    wsk_prep<<<(NSC*NSC)/256, 256>>>(sw, sb);
    wf_prep<<<(NLAY*64*64)/256, 256>>>(fw, gw);
    start_kernel<<<dim3(NV/256, 13, NB), 256>>>(x, stw, stb);

    const int dil[NLAY] = {1,2,1,2,1,2,1,2};
    int Tin = 13, parity = 0;
    for (int i = 0; i < NLAY; i++) {
        int d = dil[i], Tout = Tin - d;
        gated_mma<<<dim3(NV/128, Tout, NB), 256>>>(fb, gb, i, Tin, d, parity);

        if (i < NLAY-1) {   // last layer's gcn output is dead code
            int M = NB*NRC*Tout;
            // hop 1: gx @ A_z -> H0, H2, H4
            mma_gemm<<<dim3(NV/BN, M/BM, 3), 256, GSMEM>>>(
                p_gx, p_bt, p_H,
                0L, (long)NN, 2L*HBUF,
                NV, NV, NV, NV/BK, nullptr, 4);
            // hop 2: H{0,2,4} @ A_z -> H1, H3, H5
            mma_gemm<<<dim3(NV/BN, M/BM, 3), 256, GSMEM>>>(
                p_H, p_bt, p_H + HBUF,
                2L*HBUF, (long)NN, 2L*HBUF,
                NV, NV, NV, NV/BK, nullptr, 4);
            gcn_mma<<<dim3(NV/128, Tout, NB), 256, GCN_SMEM>>>(
                gcnb, bng, bnb, bnm, bnv, i, Tin, d, parity);
        }
        parity ^= 1;
        Tin = Tout;
    }

    // skt[bv][j] = relu(gxl[bv][:] . wsk[j][:] + bsk[j])  (fp16 out)
    mma_gemm<<<dim3(NSC/BN, (NB*NV)/BM, 1), 256, GSMEM>>>(
        p_gxl, p_wsk, p_skt,
        0L, 0L, 0L,
        NSC, NSC, NSC, NSC/BK, p_bsk, 1|4);
    w1r_kernel<<<(NEC*NSC)/256, 256>>>(e1w);
    // E1 = relu(skt @ e1w^T + b1)
    mma_gemm<<<dim3(NEC/BN, (NB*NV)/BM, 1), 256, GSMEM>>>(
        p_skt, p_w1r, p_e1,
        0L, 0L, 0L,
        NSC, NSC, NEC, NSC/BK, e1b, 1);
    end2_kernel<<<(NB*NV)/8, 256>>>(e2w, e2b, (float*)d_out);
}

// round 15
// speedup vs baseline: 1.1445x; 1.0423x over previous
#include <cuda_runtime.h>
#include <cuda_fp16.h>
#include <math.h>
#include <stdint.h>

// ---------------- problem constants ----------------
#define NB   16
#define NV   2048
#define NRC  32
#define NSC  256
#define NEC  512
#define NOUT 12
#define NLAY 8
#define NN   (NV*NV)
#define XBUF (NB*NRC*13*NV)
#define HBUF (NB*NRC*12*NV)

// ---------------- device scratch ----------------
__device__ float  g_adp [NN];
__device__ __half g_bt  [3*NN];          // fp16 transposed supports [z][n][k]
__device__ float  g_xa  [XBUF];
__device__ float  g_xb  [XBUF];
__device__ __half g_gx  [HBUF];
__device__ __half g_H   [6*HBUF];
__device__ __half g_gxl [NB*NV*NSC];     // last-timestep gated outs [bv][l*32+c]
__device__ __half g_wsk [NSC*NSC];       // stacked skip weights [j][l*32+c]
__device__ float  g_bsk [NSC];           // summed skip bias
__device__ __half g_skt [NB*NV*NSC];     // relu'd skip, [bv][j] fp16
__device__ float  g_e1  [NB*NV*NEC];
__device__ __half g_w1r [NEC*NSC];       // fp16 e1w, already [n][k]
__device__ __half g_wg  [NLAY*NRC*224];  // gcn weights fp16 [l][o][k]
__device__ __half g_wf  [NLAY*64*64];    // gated weights [l][q=2o+isg][k=2c+tap]

// ---------------- helpers ----------------
__device__ __forceinline__ float tanh_fast(float x) {
    float y; asm("tanh.approx.f32 %0, %1;" : "=f"(y) : "f"(x));
    return y;
}
__device__ __forceinline__ uint32_t smem_u32(const void* p) {
    uint32_t a;
    asm("{ .reg .u64 t; cvta.to.shared.u64 t, %1; cvt.u32.u64 %0, t; }" : "=r"(a) : "l"(p));
    return a;
}
__device__ __forceinline__ void cp_async16(uint32_t dst, const void* src) {
    asm volatile("cp.async.cg.shared.global [%0], [%1], 16;" :: "r"(dst), "l"(src));
}
#define CP_COMMIT() asm volatile("cp.async.commit_group;" ::: "memory")

__device__ __forceinline__ void mma_f16_16x8x16(
    float& d0, float& d1, float& d2, float& d3,
    uint32_t a0, uint32_t a1, uint32_t a2, uint32_t a3,
    uint32_t b0, uint32_t b1)
{
    asm volatile(
        "mma.sync.aligned.m16n8k16.row.col.f32.f16.f16.f32 "
        "{%0,%1,%2,%3}, {%4,%5,%6,%7}, {%8,%9}, {%0,%1,%2,%3};"
        : "+f"(d0), "+f"(d1), "+f"(d2), "+f"(d3)
        : "r"(a0), "r"(a1), "r"(a2), "r"(a3), "r"(b0), "r"(b1));
}
__device__ __forceinline__ void ldsm_x4(
    uint32_t& r0, uint32_t& r1, uint32_t& r2, uint32_t& r3, uint32_t addr)
{
    asm volatile("ldmatrix.sync.aligned.m8n8.x4.shared.b16 {%0,%1,%2,%3}, [%4];"
        : "=r"(r0), "=r"(r1), "=r"(r2), "=r"(r3) : "r"(addr));
}
__device__ __forceinline__ void ldsm_x4_t(
    uint32_t& r0, uint32_t& r1, uint32_t& r2, uint32_t& r3, uint32_t addr)
{
    asm volatile("ldmatrix.sync.aligned.m8n8.x4.trans.shared.b16 {%0,%1,%2,%3}, [%4];"
        : "=r"(r0), "=r"(r1), "=r"(r2), "=r"(r3) : "r"(addr));
}

// ---------------- fp16 HMMA GEMM (R11 config): C[M,N] = X[M,K] @ B[N,K]^T ----------------
#define BM 128
#define BN 128
#define BK 64
#define KPAD_H 72
#define STG_H (BM*KPAD_H)
#define NSTAGE 3
#define GSMEM (NSTAGE*2*STG_H*2)

__global__ void __launch_bounds__(256) mma_gemm(
    const __half* __restrict__ X, const __half* __restrict__ B, void* __restrict__ Cv,
    long sX, long sB, long sC,
    int lda, int ldb, int ldc, int nkt,
    const float* __restrict__ bias, int flags)
{
    extern __shared__ __half sm[];

    int z = blockIdx.z;
    X += (size_t)z*sX;
    B += (size_t)z*sB;
    int m0 = blockIdx.y*BM, n0 = blockIdx.x*BN;

    int tid = threadIdx.x, wid = tid >> 5, lane = tid & 31;
    int wm = wid & 3, wn = wid >> 2;
    int lq = lane >> 2, lr = lane & 3;
    int lane15 = lane & 15, laneh = lane >> 4;

    uint32_t sbase = smem_u32(sm);

    auto load_stage = [&](int s, int k0) {
        uint32_t da = sbase + (uint32_t)(s*2*STG_H)*2;
        uint32_t db = da + (uint32_t)STG_H*2;
        const __half* xs = X + (size_t)m0*lda + k0;
        const __half* bs = B + (size_t)n0*ldb + k0;
        #pragma unroll
        for (int i = 0; i < 4; i++) {
            int l = tid + i*256;
            int row = l >> 3, seg = l & 7;
            uint32_t off = (uint32_t)(row*KPAD_H + seg*8)*2;
            cp_async16(da + off, xs + (size_t)row*lda + seg*8);
            cp_async16(db + off, bs + (size_t)row*ldb + seg*8);
        }
    };

    float acc[2][8][4];
    #pragma unroll
    for (int mt = 0; mt < 2; mt++)
        #pragma unroll
        for (int nt = 0; nt < 8; nt++)
            #pragma unroll
            for (int k = 0; k < 4; k++) acc[mt][nt][k] = 0.f;

    load_stage(0, 0);  CP_COMMIT();
    if (nkt > 1) load_stage(1, BK);
    CP_COMMIT();

    uint32_t aoff0 = (uint32_t)((wm*32 + lane15)*KPAD_H + 8*laneh);
    uint32_t aoff1 = aoff0 + 16u*KPAD_H;
    uint32_t boff  = (uint32_t)(STG_H + (wn*64 + lane15)*KPAD_H + 8*laneh);

    for (int kt = 0; kt < nkt; kt++) {
        asm volatile("cp.async.wait_group 1;" ::: "memory");
        __syncthreads();

        if (kt + 2 < nkt) load_stage((kt+2) % NSTAGE, (kt+2)*BK);
        CP_COMMIT();

        uint32_t slab = sbase + (uint32_t)((kt % NSTAGE)*2*STG_H)*2;

        uint32_t a[2][2][4], b[2][8][2];
        ldsm_x4(a[0][0][0], a[0][0][1], a[0][0][2], a[0][0][3], slab + aoff0*2);
        ldsm_x4(a[0][1][0], a[0][1][1], a[0][1][2], a[0][1][3], slab + aoff1*2);
        #pragma unroll
        for (int nt2 = 0; nt2 < 4; nt2++) {
            uint32_t r0, r1, r2, r3;
            ldsm_x4(r0, r1, r2, r3, slab + (boff + nt2*16u*KPAD_H)*2);
            b[0][2*nt2][0] = r0; b[0][2*nt2+1][0] = r1;
            b[0][2*nt2][1] = r2; b[0][2*nt2+1][1] = r3;
        }

        #pragma unroll
        for (int k16 = 0; k16 < BK/16; k16++) {
            int cur = k16 & 1, nxt = cur ^ 1;
            if (k16 + 1 < BK/16) {
                uint32_t kk = (uint32_t)((k16 + 1)*16)*2;
                ldsm_x4(a[nxt][0][0], a[nxt][0][1], a[nxt][0][2], a[nxt][0][3],
                        slab + aoff0*2 + kk);
                ldsm_x4(a[nxt][1][0], a[nxt][1][1], a[nxt][1][2], a[nxt][1][3],
                        slab + aoff1*2 + kk);
                #pragma unroll
                for (int nt2 = 0; nt2 < 4; nt2++) {
                    uint32_t r0, r1, r2, r3;
                    ldsm_x4(r0, r1, r2, r3, slab + (boff + nt2*16u*KPAD_H)*2 + kk);
                    b[nxt][2*nt2][0] = r0; b[nxt][2*nt2+1][0] = r1;
                    b[nxt][2*nt2][1] = r2; b[nxt][2*nt2+1][1] = r3;
                }
            }
            #pragma unroll
            for (int mt = 0; mt < 2; mt++)
                #pragma unroll
                for (int nt = 0; nt < 8; nt++)
                    mma_f16_16x8x16(acc[mt][nt][0], acc[mt][nt][1], acc[mt][nt][2], acc[mt][nt][3],
                                    a[cur][mt][0], a[cur][mt][1], a[cur][mt][2], a[cur][mt][3],
                                    b[cur][nt][0], b[cur][nt][1]);
        }
    }

    int rowa = m0 + wm*32 + lq;
    int colb = n0 + wn*64 + 2*lr;
    #pragma unroll
    for (int mt = 0; mt < 2; mt++) {
        #pragma unroll
        for (int nt = 0; nt < 8; nt++) {
            float v0 = acc[mt][nt][0], v1 = acc[mt][nt][1];
            float v2 = acc[mt][nt][2], v3 = acc[mt][nt][3];
            if (bias) {
                float b0 = bias[colb + nt*8], b1 = bias[colb + nt*8 + 1];
                v0 += b0; v1 += b1; v2 += b0; v3 += b1;
            }
            if (flags & 1) {
                v0 = fmaxf(v0, 0.f); v1 = fmaxf(v1, 0.f);
                v2 = fmaxf(v2, 0.f); v3 = fmaxf(v3, 0.f);
            }
            if (flags & 4) {
                __half* Ch = (__half*)Cv + (size_t)z*sC;
                __half2 h0 = __floats2half2_rn(v0, v1);
                __half2 h1 = __floats2half2_rn(v2, v3);
                *(__half2*)(Ch + (size_t)(rowa + mt*16)*ldc + colb + nt*8) = h0;
                *(__half2*)(Ch + (size_t)(rowa + mt*16 + 8)*ldc + colb + nt*8) = h1;
            } else {
                float* Cf = (float*)Cv + (size_t)z*sC;
                float2 w0; w0.x = v0; w0.y = v1;
                float2 w1; w1.x = v2; w1.y = v3;
                *(float2*)(Cf + (size_t)(rowa + mt*16)*ldc + colb + nt*8) = w0;
                *(float2*)(Cf + (size_t)(rowa + mt*16 + 8)*ldc + colb + nt*8) = w1;
            }
        }
    }
}

// ---------------- adp = softmax(relu(nv1 @ nv2), axis=1) ----------------
__global__ void adp_kernel(const float* __restrict__ nv1, const float* __restrict__ nv2)
{
    int row = blockIdx.x;
    int tid = threadIdx.x;
    __shared__ float v1[10];
    __shared__ float red[256];
    if (tid < 10) v1[tid] = nv1[row*10 + tid];
    __syncthreads();
    float vals[8];
    float mx = -1e30f;
    #pragma unroll
    for (int j = 0; j < 8; j++) {
        int col = tid + j*256;
        float s = 0.f;
        #pragma unroll
        for (int k = 0; k < 10; k++) s += v1[k]*nv2[k*NV + col];
        s = fmaxf(s, 0.f);
        vals[j] = s;
        mx = fmaxf(mx, s);
    }
    red[tid] = mx; __syncthreads();
    for (int s2 = 128; s2 > 0; s2 >>= 1) {
        if (tid < s2) red[tid] = fmaxf(red[tid], red[tid+s2]);
        __syncthreads();
    }
    mx = red[0];
    __syncthreads();
    float sum = 0.f;
    #pragma unroll
    for (int j = 0; j < 8; j++) { vals[j] = expf(vals[j] - mx); sum += vals[j]; }
    red[tid] = sum; __syncthreads();
    for (int s2 = 128; s2 > 0; s2 >>= 1) {
        if (tid < s2) red[tid] += red[tid+s2];
        __syncthreads();
    }
    float inv = 1.f/red[0];
    #pragma unroll
    for (int j = 0; j < 8; j++) g_adp[row*NV + tid + j*256] = vals[j]*inv;
}

// ---------------- build fp16 transposed supports ----------------
__global__ void bt_kernel(const float* __restrict__ A)
{
    __shared__ float tile[32][33];
    int z = blockIdx.z;
    const float* S = (z < 2) ? (A + (size_t)z*NN) : g_adp;
    int r0 = blockIdx.y*32, c0 = blockIdx.x*32;
    int x = threadIdx.x & 31, y = threadIdx.x >> 5;
    #pragma unroll
    for (int i = 0; i < 32; i += 8)
        tile[y+i][x] = S[(size_t)(r0 + y + i)*NV + c0 + x];
    __syncthreads();
    #pragma unroll
    for (int i = 0; i < 32; i += 8)
        g_bt[((size_t)z*NV + c0 + y + i)*NV + r0 + x] = __float2half(tile[x][y+i]);
}

// ---------------- merged one-time weight prep ----------------
__global__ void prep_kernel(const float* __restrict__ gcnw,
                            const float* __restrict__ sw, const float* __restrict__ sb,
                            const float* __restrict__ fw, const float* __restrict__ gw,
                            const float* __restrict__ e1w)
{
    int idx = blockIdx.x*256 + threadIdx.x;
    if (idx < NLAY*NRC*224) {                 // gcn weights -> fp16
        g_wg[idx] = __float2half(gcnw[idx]);
        return;
    }
    idx -= NLAY*NRC*224;
    if (idx < NSC*NSC) {                      // stacked skip weights + bias sum
        int j = idx >> 8, k = idx & 255;
        int l = k >> 5, c = k & 31;
        g_wsk[idx] = __float2half(sw[(l*NSC + j)*NRC + c]);
        if (idx < NSC) {
            float s = 0.f;
            #pragma unroll
            for (int ll = 0; ll < NLAY; ll++) s += sb[ll*NSC + idx];
            g_bsk[idx] = s;
        }
        return;
    }
    idx -= NSC*NSC;
    if (idx < NLAY*64*64) {                   // gated weight pack
        int l = idx >> 12, rem = idx & 4095;
        int q = rem >> 6, k = rem & 63;
        int o = q >> 1, isg = q & 1;
        int c = k >> 1, tap = k & 1;
        const float* W = isg ? gw : fw;
        g_wf[idx] = __float2half(W[((l*NRC + o)*NRC + c)*2 + tap]);
        return;
    }
    idx -= NLAY*64*64;
    if (idx < NEC*NSC)                        // end1 weights -> fp16
        g_w1r[idx] = __float2half(e1w[idx]);
}
#define PREP_TOTAL (NLAY*NRC*224 + NSC*NSC + NLAY*64*64 + NEC*NSC)

// ---------------- pad + start 1x1 conv ----------------
__global__ void start_kernel(const float* __restrict__ x,
                             const float* __restrict__ sw, const float* __restrict__ sb)
{
    int v = blockIdx.x*256 + threadIdx.x;
    int t = blockIdx.y, b = blockIdx.z;
    float in0 = 0.f, in1 = 0.f;
    if (t > 0) {
        in0 = x[((b*2+0)*NV + v)*12 + (t-1)];
        in1 = x[((b*2+1)*NV + v)*12 + (t-1)];
    }
    #pragma unroll
    for (int o = 0; o < NRC; o++) {
        g_xa[((b*NRC+o)*13 + t)*NV + v] = sb[o] + sw[o*2]*in0 + sw[o*2+1]*in1;
    }
}

// ---------------- gated dilated conv via HMMA ----------------
#define GPAD 72
__global__ void __launch_bounds__(256) gated_mma(
    const float* __restrict__ fb, const float* __restrict__ gb,
    int layer, int Tin, int d, int parity)
{
    __shared__ __half Xs[128*GPAD];
    __shared__ __half Ws[64*GPAD];
    __shared__ __half Os[32*136];
    __shared__ float sfb[NRC], sgb[NRC];

    const float* xin = parity ? g_xb : g_xa;
    int Tout = Tin - d;
    int v0 = blockIdx.x*128;
    int t = blockIdx.y, b = blockIdx.z;
    int tid = threadIdx.x, wid = tid >> 5, lane = tid & 31;
    int lq = lane >> 2, lr = lane & 3;
    int lane15 = lane & 15, laneh = lane >> 4;

    const __half* wsrc = g_wf + layer*64*64;
    for (int i = tid; i < 64*32; i += 256) {
        int row = i >> 5, col2 = (i & 31)*2;
        *(uint32_t*)&Ws[row*GPAD + col2] = *(const uint32_t*)&wsrc[row*64 + col2];
    }
    if (tid < NRC) {
        sfb[tid] = fb[layer*NRC + tid];
        sgb[tid] = gb[layer*NRC + tid];
    }
    {
        int v = tid & 127;
        #pragma unroll
        for (int i = 0; i < 32; i++) {
            int r = i*2 + (tid >> 7);
            int c = r >> 1, tap = r & 1;
            float val = xin[((b*NRC + c)*Tin + t + tap*d)*NV + v0 + v];
            Xs[v*GPAD + r] = __float2half(val);
        }
    }
    __syncthreads();

    uint32_t sx = smem_u32(Xs), sw_ = smem_u32(Ws);
    float acc[8][4];
    #pragma unroll
    for (int nt = 0; nt < 8; nt++)
        #pragma unroll
        for (int k = 0; k < 4; k++) acc[nt][k] = 0.f;

    uint32_t axa = sx + (uint32_t)((wid*16 + lane15)*GPAD + 8*laneh)*2;
    uint32_t bxa = sw_ + (uint32_t)(lane15*GPAD + 8*laneh)*2;

    #pragma unroll
    for (int k16 = 0; k16 < 4; k16++) {
        uint32_t kk = (uint32_t)(k16*16)*2;
        uint32_t a0, a1, a2, a3;
        ldsm_x4(a0, a1, a2, a3, axa + kk);
        uint32_t bfr[8][2];
        #pragma unroll
        for (int nt2 = 0; nt2 < 4; nt2++) {
            uint32_t r0, r1, r2, r3;
            ldsm_x4(r0, r1, r2, r3, bxa + (uint32_t)(nt2*16*GPAD)*2 + kk);
            bfr[2*nt2][0] = r0; bfr[2*nt2+1][0] = r1;
            bfr[2*nt2][1] = r2; bfr[2*nt2+1][1] = r3;
        }
        #pragma unroll
        for (int nt = 0; nt < 8; nt++)
            mma_f16_16x8x16(acc[nt][0], acc[nt][1], acc[nt][2], acc[nt][3],
                            a0, a1, a2, a3, bfr[nt][0], bfr[nt][1]);
    }

    #pragma unroll
    for (int nt = 0; nt < 8; nt++) {
        int o = nt*4 + lr;
        float fbv = sfb[o], gbv = sgb[o];
        float f0 = tanh_fast(acc[nt][0] + fbv);
        float g0 = 0.5f*tanh_fast(0.5f*(acc[nt][1] + gbv)) + 0.5f;
        float f1 = tanh_fast(acc[nt][2] + fbv);
        float g1 = 0.5f*tanh_fast(0.5f*(acc[nt][3] + gbv)) + 0.5f;
        Os[o*136 + wid*16 + lq]     = __float2half(f0*g0);
        Os[o*136 + wid*16 + lq + 8] = __float2half(f1*g1);
    }
    __syncthreads();

    #pragma unroll
    for (int i = 0; i < 2; i++) {
        int idx = tid + i*256;
        int row = idx >> 4, ch = idx & 15;
        uint4 val = *(const uint4*)&Os[row*136 + ch*8];
        *(uint4*)&g_gx[((size_t)(b*NRC + row)*Tout + t)*NV + v0 + ch*8] = val;
    }
    if (t == Tout - 1) {
        int v = tid >> 1, oh = tid & 1;
        __half hb[16];
        #pragma unroll
        for (int i = 0; i < 16; i++) hb[i] = Os[(oh*16 + i)*136 + v];
        uint4* dst = (uint4*)(g_gxl + ((size_t)b*NV + v0 + v)*NSC + layer*NRC + oh*16);
        const uint4* src = (const uint4*)hb;
        dst[0] = src[0]; dst[1] = src[1];
    }
}

// ---------------- gcn via HMMA, k-major staging + ldmatrix.trans ----------------
// C[128v,32o] = Xcat[128v,224k] @ W[32o,224k]^T. Xk stored k-major [224][136].
#define XKROW 136
#define WPAD 232
#define GCN_SMEM (224*XKROW*2 + 32*WPAD*2 + 32*132*4 + 512)

__global__ void __launch_bounds__(256) gcn_mma(
    const float* __restrict__ gb,
    const float* __restrict__ bng, const float* __restrict__ bnb,
    const float* __restrict__ bnm, const float* __restrict__ bnv,
    int layer, int Tin, int d, int parity)
{
    extern __shared__ __half dsm[];
    __half* Xk = dsm;                                   // 224 x 136 halves
    __half* Ws = dsm + 224*XKROW;                       // 32 x 232 halves
    float*  Os = (float*)(dsm + 224*XKROW + 32*WPAD);   // 32 x 132 floats
    float*  cst = Os + 32*132;

    int Tout = Tin - d;
    const float* xin  = parity ? g_xb : g_xa;
    float*       xout = parity ? g_xa : g_xb;
    int v0 = blockIdx.x*128;
    int t = blockIdx.y, b = blockIdx.z;
    int tid = threadIdx.x, wid = tid >> 5, lane = tid & 31;
    int lq = lane >> 2, lr = lane & 3;
    int lane15 = lane & 15, laneh = lane >> 4;

    // stage W [32o][224k]
    const __half* wsrc = g_wg + layer*NRC*224;
    for (int i = tid; i < 32*28; i += 256) {
        int o = i / 28, c = i % 28;
        *(uint4*)&Ws[o*WPAD + c*8] = *(const uint4*)&wsrc[o*224 + c*8];
    }
    if (tid < NRC) {
        cst[tid]      = bng[layer*NRC+tid]*rsqrtf(bnv[layer*NRC+tid] + 1e-5f);
        cst[32 + tid] = bnb[layer*NRC+tid];
        cst[64 + tid] = bnm[layer*NRC+tid];
        cst[96 + tid] = gb [layer*NRC+tid];
    }

    // stage Xcat k-major: 224 k-rows x 128 v, vectorized uint4 both sides
    {
        #pragma unroll
        for (int i = 0; i < 14; i++) {
            int idx = tid + i*256;            // 0..3583
            int vq = idx & 15, gc = idx >> 4; // gc = global k index / channel
            int g = gc >> 5, cc = gc & 31;
            const __half* Hp = (g == 0) ? g_gx : (g_H + (size_t)(g-1)*HBUF);
            uint4 val = *(const uint4*)(Hp + ((size_t)(b*NRC + cc)*Tout + t)*NV + v0 + vq*8);
            *(uint4*)&Xk[gc*XKROW + vq*8] = val;
        }
    }
    __syncthreads();

    uint32_t sxk = smem_u32(Xk), sw_ = smem_u32(Ws);
    float acc[4][4];
    #pragma unroll
    for (int nt = 0; nt < 4; nt++)
        #pragma unroll
        for (int k = 0; k < 4; k++) acc[nt][k] = 0.f;

    // ldmatrix.trans lane addressing: lanes 0-7 m0(k0-7,v+0), 8-15 m1(k0-7,v+8),
    // 16-23 m2(k8-15,v+0), 24-31 m3(k8-15,v+8)
    int ka = (lane & 7) + 8*((lane >> 4) & 1);
    int va = wid*16 + 8*((lane >> 3) & 1);
    uint32_t axk = sxk + (uint32_t)(ka*XKROW + va)*2;
    uint32_t bxa = sw_ + (uint32_t)(lane15*WPAD + 8*laneh)*2;

    #pragma unroll
    for (int kc = 0; kc < 14; kc++) {
        uint32_t a0, a1, a2, a3;
        ldsm_x4_t(a0, a1, a2, a3, axk + (uint32_t)(kc*16*XKROW)*2);
        uint32_t bfr[4][2];
        #pragma unroll
        for (int nt2 = 0; nt2 < 2; nt2++) {
            uint32_t r0, r1, r2, r3;
            ldsm_x4(r0, r1, r2, r3, bxa + (uint32_t)(nt2*16*WPAD + kc*16)*2);
            bfr[2*nt2][0] = r0; bfr[2*nt2+1][0] = r1;
            bfr[2*nt2][1] = r2; bfr[2*nt2+1][1] = r3;
        }
        #pragma unroll
        for (int nt = 0; nt < 4; nt++)
            mma_f16_16x8x16(acc[nt][0], acc[nt][1], acc[nt][2], acc[nt][3],
                            a0, a1, a2, a3, bfr[nt][0], bfr[nt][1]);
    }

    // scatter acc -> Os[o][v]
    #pragma unroll
    for (int nt = 0; nt < 4; nt++) {
        int o = nt*8 + 2*lr;
        int v = wid*16 + lq;
        Os[o*132 + v]         = acc[nt][0];
        Os[(o+1)*132 + v]     = acc[nt][1];
        Os[o*132 + v + 8]     = acc[nt][2];
        Os[(o+1)*132 + v + 8] = acc[nt][3];
    }
    __syncthreads();

    // fused bias + residual + BN, coalesced
    #pragma unroll
    for (int i = 0; i < 16; i++) {
        int idx = tid + i*256;
        int o = idx >> 7, v = idx & 127;
        float val = Os[o*132 + v] + cst[96 + o]
                  + xin[((size_t)(b*NRC + o)*Tin + t + d)*NV + v0 + v];
        val = (val - cst[64 + o])*cst[o] + cst[32 + o];
        xout[((size_t)(b*NRC + o)*Tout + t)*NV + v0 + v] = val;
    }
}

// ---------------- end2 ----------------
__global__ __launch_bounds__(256) void end2_kernel(
    const float* __restrict__ e2w, const float* __restrict__ e2b, float* __restrict__ out)
{
    __shared__ float w[NOUT*NEC];
    __shared__ float sb[NOUT];
    for (int i = threadIdx.x; i < NOUT*NEC; i += 256) w[i] = e2w[i];
    if (threadIdx.x < NOUT) sb[threadIdx.x] = e2b[threadIdx.x];
    __syncthreads();

    int warp = threadIdx.x >> 5, lane = threadIdx.x & 31;
    int row = blockIdx.x*8 + warp;
    const float* e1r = g_e1 + (size_t)row*NEC;
    float r[16];
    #pragma unroll
    for (int k = 0; k < 16; k++) r[k] = e1r[lane + k*32];
    int b = row >> 11, v = row & (NV-1);
    #pragma unroll
    for (int o = 0; o < NOUT; o++) {
        float s = 0.f;
        #pragma unroll
        for (int k = 0; k < 16; k++) s += r[k]*w[o*NEC + lane + k*32];
        #pragma unroll
        for (int off = 16; off; off >>= 1) s += __shfl_xor_sync(0xffffffffu, s, off);
        if (lane == 0) out[((size_t)b*NOUT + o)*NV + v] = s + sb[o];
    }
}

// ---------------- launch ----------------
extern "C" void kernel_launch(void* const* d_in, const int* in_sizes, int n_in,
                              void* d_out, int out_size)
{
    (void)in_sizes; (void)n_in; (void)out_size;
    const float* x    = (const float*)d_in[0];
    const float* A    = (const float*)d_in[1];
    const float* nv1  = (const float*)d_in[2];
    const float* nv2  = (const float*)d_in[3];
    const float* fw   = (const float*)d_in[4];
    const float* fb   = (const float*)d_in[5];
    const float* gw   = (const float*)d_in[6];
    const float* gb   = (const float*)d_in[7];
    const float* sw   = (const float*)d_in[8];
    const float* sb   = (const float*)d_in[9];
    const float* gcnw = (const float*)d_in[10];
    const float* gcnb = (const float*)d_in[11];
    const float* bng  = (const float*)d_in[12];
    const float* bnb  = (const float*)d_in[13];
    const float* bnm  = (const float*)d_in[14];
    const float* bnv  = (const float*)d_in[15];
    const float* stw  = (const float*)d_in[16];
    const float* stb  = (const float*)d_in[17];
    const float* e1w  = (const float*)d_in[18];
    const float* e1b  = (const float*)d_in[19];
    const float* e2w  = (const float*)d_in[20];
    const float* e2b  = (const float*)d_in[21];

    __half *p_gx, *p_H, *p_skt, *p_w1r, *p_bt, *p_gxl, *p_wsk;
    float  *p_e1, *p_bsk;
    cudaGetSymbolAddress((void**)&p_gx,   g_gx);
    cudaGetSymbolAddress((void**)&p_H,    g_H);
    cudaGetSymbolAddress((void**)&p_skt,  g_skt);
    cudaGetSymbolAddress((void**)&p_e1,   g_e1);
    cudaGetSymbolAddress((void**)&p_w1r,  g_w1r);
    cudaGetSymbolAddress((void**)&p_bt,   g_bt);
    cudaGetSymbolAddress((void**)&p_gxl,  g_gxl);
    cudaGetSymbolAddress((void**)&p_wsk,  g_wsk);
    cudaGetSymbolAddress((void**)&p_bsk,  g_bsk);

    cudaFuncSetAttribute(mma_gemm, cudaFuncAttributeMaxDynamicSharedMemorySize, GSMEM);
    cudaFuncSetAttribute(gcn_mma,  cudaFuncAttributeMaxDynamicSharedMemorySize, GCN_SMEM);

    adp_kernel<<<NV, 256>>>(nv1, nv2);
    bt_kernel<<<dim3(NV/32, NV/32, 3), 256>>>(A);
    prep_kernel<<<(PREP_TOTAL + 255)/256, 256>>>(gcnw, sw, sb, fw, gw, e1w);
    start_kernel<<<dim3(NV/256, 13, NB), 256>>>(x, stw, stb);

    const int dil[NLAY] = {1,2,1,2,1,2,1,2};
    int Tin = 13, parity = 0;
    for (int i = 0; i < NLAY; i++) {
        int d = dil[i], Tout = Tin - d;
        gated_mma<<<dim3(NV/128, Tout, NB), 256>>>(fb, gb, i, Tin, d, parity);

        if (i < NLAY-1) {   // last layer's gcn output is dead code
            int M = NB*NRC*Tout;
            // hop 1: gx @ A_z -> H0, H2, H4
            mma_gemm<<<dim3(NV/BN, M/BM, 3), 256, GSMEM>>>(
                p_gx, p_bt, p_H,
                0L, (long)NN, 2L*HBUF,
                NV, NV, NV, NV/BK, nullptr, 4);
            // hop 2: H{0,2,4} @ A_z -> H1, H3, H5
            mma_gemm<<<dim3(NV/BN, M/BM, 3), 256, GSMEM>>>(
                p_H, p_bt, p_H + HBUF,
                2L*HBUF, (long)NN, 2L*HBUF,
                NV, NV, NV, NV/BK, nullptr, 4);
            gcn_mma<<<dim3(NV/128, Tout, NB), 256, GCN_SMEM>>>(
                gcnb, bng, bnb, bnm, bnv, i, Tin, d, parity);
        }
        parity ^= 1;
        Tin = Tout;
    }

    // skt[bv][j] = relu(gxl[bv][:] . wsk[j][:] + bsk[j])  (fp16 out)
    mma_gemm<<<dim3(NSC/BN, (NB*NV)/BM, 1), 256, GSMEM>>>(
        p_gxl, p_wsk, p_skt,
        0L, 0L, 0L,
        NSC, NSC, NSC, NSC/BK, p_bsk, 1|4);
    // E1 = relu(skt @ e1w^T + b1)
    mma_gemm<<<dim3(NEC/BN, (NB*NV)/BM, 1), 256, GSMEM>>>(
        p_skt, p_w1r, p_e1,
        0L, 0L, 0L,
        NSC, NSC, NEC, NSC/BK, e1b, 1);
    end2_kernel<<<(NB*NV)/8, 256>>>(e2w, e2b, (float*)d_out);
}

// round 16
// speedup vs baseline: 1.1581x; 1.0120x over previous
#include <cuda_runtime.h>
#include <cuda_fp16.h>
#include <math.h>
#include <stdint.h>

// ---------------- problem constants ----------------
#define NB   16
#define NV   2048
#define NRC  32
#define NSC  256
#define NEC  512
#define NOUT 12
#define NLAY 8
#define NN   (NV*NV)
#define XBUF (NB*NRC*13*NV)
#define HBUF (NB*NRC*12*NV)

// ---------------- device scratch ----------------
__device__ float  g_adp [NN];
__device__ __half g_bt  [3*NN];          // fp16 transposed supports [z][n][k]
__device__ float  g_xa  [XBUF];
__device__ float  g_xb  [XBUF];
__device__ __half g_gx  [HBUF];
__device__ __half g_H   [6*HBUF];
__device__ __half g_gxl [NB*NV*NSC];     // last-timestep gated outs [bv][l*32+c]
__device__ __half g_wsk [NSC*NSC];       // stacked skip weights [j][l*32+c]
__device__ float  g_bsk [NSC];           // summed skip bias
__device__ __half g_w1r [NEC*NSC];       // fp16 e1w, already [n][k]
__device__ __half g_wg  [NLAY*NRC*224];  // gcn weights fp16 [l][o][k]
__device__ __half g_wf  [NLAY*64*64];    // gated weights [l][q=2o+isg][k=2c+tap]

// ---------------- helpers ----------------
__device__ __forceinline__ float tanh_fast(float x) {
    float y; asm("tanh.approx.f32 %0, %1;" : "=f"(y) : "f"(x));
    return y;
}
__device__ __forceinline__ uint32_t smem_u32(const void* p) {
    uint32_t a;
    asm("{ .reg .u64 t; cvta.to.shared.u64 t, %1; cvt.u32.u64 %0, t; }" : "=r"(a) : "l"(p));
    return a;
}
__device__ __forceinline__ void cp_async16(uint32_t dst, const void* src) {
    asm volatile("cp.async.cg.shared.global [%0], [%1], 16;" :: "r"(dst), "l"(src));
}
#define CP_COMMIT() asm volatile("cp.async.commit_group;" ::: "memory")

__device__ __forceinline__ void mma_f16_16x8x16(
    float& d0, float& d1, float& d2, float& d3,
    uint32_t a0, uint32_t a1, uint32_t a2, uint32_t a3,
    uint32_t b0, uint32_t b1)
{
    asm volatile(
        "mma.sync.aligned.m16n8k16.row.col.f32.f16.f16.f32 "
        "{%0,%1,%2,%3}, {%4,%5,%6,%7}, {%8,%9}, {%0,%1,%2,%3};"
        : "+f"(d0), "+f"(d1), "+f"(d2), "+f"(d3)
        : "r"(a0), "r"(a1), "r"(a2), "r"(a3), "r"(b0), "r"(b1));
}
__device__ __forceinline__ void ldsm_x4(
    uint32_t& r0, uint32_t& r1, uint32_t& r2, uint32_t& r3, uint32_t addr)
{
    asm volatile("ldmatrix.sync.aligned.m8n8.x4.shared.b16 {%0,%1,%2,%3}, [%4];"
        : "=r"(r0), "=r"(r1), "=r"(r2), "=r"(r3) : "r"(addr));
}
__device__ __forceinline__ void ldsm_x4_t(
    uint32_t& r0, uint32_t& r1, uint32_t& r2, uint32_t& r3, uint32_t addr)
{
    asm volatile("ldmatrix.sync.aligned.m8n8.x4.trans.shared.b16 {%0,%1,%2,%3}, [%4];"
        : "=r"(r0), "=r"(r1), "=r"(r2), "=r"(r3) : "r"(addr));
}

// 128m x 128n x 64k slab MMA (R11 warp layout: 8 warps 4m x 2n, warp tile 32x64).
// aAddr: smem byte addr pre-offset to (wm*32+lane15)*apadH + 8*laneh + slab col (halves*2)
// bAddr: smem byte addr pre-offset to (wn*64+lane15)*72 + 8*laneh (halves*2)
__device__ __forceinline__ void mma_block64(
    uint32_t aAddr, int apadH, uint32_t bAddr, float (&acc)[2][8][4])
{
    #pragma unroll
    for (int k16 = 0; k16 < 4; k16++) {
        uint32_t kk = (uint32_t)(k16*16)*2;
        uint32_t a0,a1,a2,a3,a4,a5,a6,a7;
        ldsm_x4(a0,a1,a2,a3, aAddr + kk);
        ldsm_x4(a4,a5,a6,a7, aAddr + (uint32_t)(16*apadH)*2 + kk);
        uint32_t bfr[8][2];
        #pragma unroll
        for (int nt2 = 0; nt2 < 4; nt2++) {
            uint32_t r0,r1,r2,r3;
            ldsm_x4(r0,r1,r2,r3, bAddr + (uint32_t)(nt2*16*72)*2 + kk);
            bfr[2*nt2][0]=r0; bfr[2*nt2+1][0]=r1;
            bfr[2*nt2][1]=r2; bfr[2*nt2+1][1]=r3;
        }
        #pragma unroll
        for (int nt = 0; nt < 8; nt++) {
            mma_f16_16x8x16(acc[0][nt][0],acc[0][nt][1],acc[0][nt][2],acc[0][nt][3],
                            a0,a1,a2,a3, bfr[nt][0],bfr[nt][1]);
            mma_f16_16x8x16(acc[1][nt][0],acc[1][nt][1],acc[1][nt][2],acc[1][nt][3],
                            a4,a5,a6,a7, bfr[nt][0],bfr[nt][1]);
        }
    }
}

// ---------------- fp16 HMMA GEMM (R11 config + staged C writes) ----------------
#define BM 128
#define BN 128
#define BK 64
#define KPAD_H 72
#define STG_H (BM*KPAD_H)
#define NSTAGE 3
#define GSMEM (NSTAGE*2*STG_H*2)

__global__ void __launch_bounds__(256) mma_gemm(
    const __half* __restrict__ X, const __half* __restrict__ B, void* __restrict__ Cv,
    long sX, long sB, long sC,
    int lda, int ldb, int ldc, int nkt,
    const float* __restrict__ bias, int flags)
{
    extern __shared__ __half sm[];

    int z = blockIdx.z;
    X += (size_t)z*sX;
    B += (size_t)z*sB;
    int m0 = blockIdx.y*BM, n0 = blockIdx.x*BN;

    int tid = threadIdx.x, wid = tid >> 5, lane = tid & 31;
    int wm = wid & 3, wn = wid >> 2;
    int lq = lane >> 2, lr = lane & 3;
    int lane15 = lane & 15, laneh = lane >> 4;

    uint32_t sbase = smem_u32(sm);

    auto load_stage = [&](int s, int k0) {
        uint32_t da = sbase + (uint32_t)(s*2*STG_H)*2;
        uint32_t db = da + (uint32_t)STG_H*2;
        const __half* xs = X + (size_t)m0*lda + k0;
        const __half* bs = B + (size_t)n0*ldb + k0;
        #pragma unroll
        for (int i = 0; i < 4; i++) {
            int l = tid + i*256;
            int row = l >> 3, seg = l & 7;
            uint32_t off = (uint32_t)(row*KPAD_H + seg*8)*2;
            cp_async16(da + off, xs + (size_t)row*lda + seg*8);
            cp_async16(db + off, bs + (size_t)row*ldb + seg*8);
        }
    };

    float acc[2][8][4];
    #pragma unroll
    for (int mt = 0; mt < 2; mt++)
        #pragma unroll
        for (int nt = 0; nt < 8; nt++)
            #pragma unroll
            for (int k = 0; k < 4; k++) acc[mt][nt][k] = 0.f;

    load_stage(0, 0);  CP_COMMIT();
    if (nkt > 1) load_stage(1, BK);
    CP_COMMIT();

    uint32_t aoff0 = (uint32_t)((wm*32 + lane15)*KPAD_H + 8*laneh);
    uint32_t aoff1 = aoff0 + 16u*KPAD_H;
    uint32_t boff  = (uint32_t)(STG_H + (wn*64 + lane15)*KPAD_H + 8*laneh);

    for (int kt = 0; kt < nkt; kt++) {
        asm volatile("cp.async.wait_group 1;" ::: "memory");
        __syncthreads();

        if (kt + 2 < nkt) load_stage((kt+2) % NSTAGE, (kt+2)*BK);
        CP_COMMIT();

        uint32_t slab = sbase + (uint32_t)((kt % NSTAGE)*2*STG_H)*2;

        uint32_t a[2][2][4], b[2][8][2];
        ldsm_x4(a[0][0][0], a[0][0][1], a[0][0][2], a[0][0][3], slab + aoff0*2);
        ldsm_x4(a[0][1][0], a[0][1][1], a[0][1][2], a[0][1][3], slab + aoff1*2);
        #pragma unroll
        for (int nt2 = 0; nt2 < 4; nt2++) {
            uint32_t r0, r1, r2, r3;
            ldsm_x4(r0, r1, r2, r3, slab + (boff + nt2*16u*KPAD_H)*2);
            b[0][2*nt2][0] = r0; b[0][2*nt2+1][0] = r1;
            b[0][2*nt2][1] = r2; b[0][2*nt2+1][1] = r3;
        }

        #pragma unroll
        for (int k16 = 0; k16 < BK/16; k16++) {
            int cur = k16 & 1, nxt = cur ^ 1;
            if (k16 + 1 < BK/16) {
                uint32_t kk = (uint32_t)((k16 + 1)*16)*2;
                ldsm_x4(a[nxt][0][0], a[nxt][0][1], a[nxt][0][2], a[nxt][0][3],
                        slab + aoff0*2 + kk);
                ldsm_x4(a[nxt][1][0], a[nxt][1][1], a[nxt][1][2], a[nxt][1][3],
                        slab + aoff1*2 + kk);
                #pragma unroll
                for (int nt2 = 0; nt2 < 4; nt2++) {
                    uint32_t r0, r1, r2, r3;
                    ldsm_x4(r0, r1, r2, r3, slab + (boff + nt2*16u*KPAD_H)*2 + kk);
                    b[nxt][2*nt2][0] = r0; b[nxt][2*nt2+1][0] = r1;
                    b[nxt][2*nt2][1] = r2; b[nxt][2*nt2+1][1] = r3;
                }
            }
            #pragma unroll
            for (int mt = 0; mt < 2; mt++)
                #pragma unroll
                for (int nt = 0; nt < 8; nt++)
                    mma_f16_16x8x16(acc[mt][nt][0], acc[mt][nt][1], acc[mt][nt][2], acc[mt][nt][3],
                                    a[cur][mt][0], a[cur][mt][1], a[cur][mt][2], a[cur][mt][3],
                                    b[cur][nt][0], b[cur][nt][1]);
        }
    }

    if (flags & 4) {
        // staged, coalesced fp16 C write
        asm volatile("cp.async.wait_group 0;" ::: "memory");
        __syncthreads();
        __half* Cs = sm;   // 128 x 136 halves, fits in stage-0 slab
        #pragma unroll
        for (int mt = 0; mt < 2; mt++) {
            #pragma unroll
            for (int nt = 0; nt < 8; nt++) {
                __half2 h0 = __floats2half2_rn(acc[mt][nt][0], acc[mt][nt][1]);
                __half2 h1 = __floats2half2_rn(acc[mt][nt][2], acc[mt][nt][3]);
                int r = wm*32 + mt*16 + lq;
                int c = wn*64 + nt*8 + 2*lr;
                *(__half2*)&Cs[r*136 + c]       = h0;
                *(__half2*)&Cs[(r+8)*136 + c]   = h1;
            }
        }
        __syncthreads();
        __half* Ch = (__half*)Cv + (size_t)z*sC;
        #pragma unroll
        for (int i = 0; i < 8; i++) {
            int idx = tid + i*256;            // 2048 chunks = 128 rows x 16
            int r = idx >> 4, ch = idx & 15;
            uint4 val = *(const uint4*)&Cs[r*136 + ch*8];
            *(uint4*)(Ch + (size_t)(m0 + r)*ldc + n0 + ch*8) = val;
        }
    } else {
        int rowa = m0 + wm*32 + lq;
        int colb = n0 + wn*64 + 2*lr;
        float* Cf = (float*)Cv + (size_t)z*sC;
        #pragma unroll
        for (int mt = 0; mt < 2; mt++) {
            #pragma unroll
            for (int nt = 0; nt < 8; nt++) {
                float v0 = acc[mt][nt][0], v1 = acc[mt][nt][1];
                float v2 = acc[mt][nt][2], v3 = acc[mt][nt][3];
                if (bias) {
                    float b0 = bias[colb + nt*8], b1 = bias[colb + nt*8 + 1];
                    v0 += b0; v1 += b1; v2 += b0; v3 += b1;
                }
                if (flags & 1) {
                    v0 = fmaxf(v0, 0.f); v1 = fmaxf(v1, 0.f);
                    v2 = fmaxf(v2, 0.f); v3 = fmaxf(v3, 0.f);
                }
                float2 w0; w0.x = v0; w0.y = v1;
                float2 w1; w1.x = v2; w1.y = v3;
                *(float2*)(Cf + (size_t)(rowa + mt*16)*ldc + colb + nt*8) = w0;
                *(float2*)(Cf + (size_t)(rowa + mt*16 + 8)*ldc + colb + nt*8) = w1;
            }
        }
    }
}

// ---------------- fused end: skt -> e1 -> out ----------------
// Per CTA: 128 bv rows. S=relu(gxl@Wsk^T+bsk)[128x256]; E1=relu(S@W1^T+b1) in 4
// passes of N=128; each pass folds into out[128x12] register partials.
#define EPAD 264
#define ESMEM (128*EPAD*2 + 128*EPAD*2 + 128*72*2 + 128*136*2 + NOUT*128*4)

__global__ void __launch_bounds__(256) end_fused(
    const float* __restrict__ e1b, const float* __restrict__ e2w,
    const float* __restrict__ e2b, float* __restrict__ out)
{
    extern __shared__ __half esm[];
    __half* Xs = esm;                      // 128 x 264
    __half* Ss = esm + 128*EPAD;           // 128 x 264
    __half* Bs = esm + 2*128*EPAD;         // 128 x 72
    __half* Es = Bs + 128*72;              // 128 x 136
    float*  se2 = (float*)(Es + 128*136);  // 12 x 128

    int row0 = blockIdx.x*128;
    int tid = threadIdx.x, wid = tid >> 5, lane = tid & 31;
    int wm = wid & 3, wn = wid >> 2;
    int lq = lane >> 2, lr = lane & 3;
    int lane15 = lane & 15, laneh = lane >> 4;

    // stage gxl tile [128][256]
    #pragma unroll
    for (int i = 0; i < 16; i++) {
        int idx = tid + i*256;             // 4096 = 128 rows x 32 chunks
        int r = idx >> 5, ch = idx & 31;
        *(uint4*)&Xs[r*EPAD + ch*8] =
            *(const uint4*)&g_gxl[(size_t)(row0 + r)*NSC + ch*8];
    }
    __syncthreads();

    uint32_t sXs = smem_u32(Xs), sSs = smem_u32(Ss), sBs = smem_u32(Bs);
    uint32_t aLaneX = (uint32_t)((wm*32 + lane15)*EPAD + 8*laneh)*2;
    uint32_t aLaneS = aLaneX;              // same geometry on Ss
    uint32_t bLane  = (uint32_t)(lane15*KPAD_H + 8*laneh)*2;
    uint32_t wnOff  = (uint32_t)(wn*64*KPAD_H)*2;

    // ---- PASS A: S = relu(gxl @ Wsk^T + bsk), two n-halves of 128 ----
    for (int nh = 0; nh < 2; nh++) {
        float acc[2][8][4];
        #pragma unroll
        for (int mt = 0; mt < 2; mt++)
            #pragma unroll
            for (int nt = 0; nt < 8; nt++)
                #pragma unroll
                for (int k = 0; k < 4; k++) acc[mt][nt][k] = 0.f;
        for (int kt = 0; kt < 4; kt++) {
            __syncthreads();
            #pragma unroll
            for (int i = 0; i < 4; i++) {
                int idx = tid + i*256;     // 1024 = 128 rows x 8 segs
                int r = idx >> 3, s = idx & 7;
                *(uint4*)&Bs[r*KPAD_H + s*8] =
                    *(const uint4*)&g_wsk[(nh*128 + r)*NSC + kt*64 + s*8];
            }
            __syncthreads();
            mma_block64(sXs + aLaneX + (uint32_t)(kt*64)*2, EPAD,
                        sBs + bLane + wnOff, acc);
        }
        // epilogue -> Ss
        #pragma unroll
        for (int mt = 0; mt < 2; mt++) {
            #pragma unroll
            for (int nt = 0; nt < 8; nt++) {
                int r = wm*32 + mt*16 + lq;
                int c = wn*64 + nt*8 + 2*lr;
                float b0 = g_bsk[nh*128 + c], b1 = g_bsk[nh*128 + c + 1];
                __half2 h0 = __floats2half2_rn(fmaxf(acc[mt][nt][0] + b0, 0.f),
                                               fmaxf(acc[mt][nt][1] + b1, 0.f));
                __half2 h1 = __floats2half2_rn(fmaxf(acc[mt][nt][2] + b0, 0.f),
                                               fmaxf(acc[mt][nt][3] + b1, 0.f));
                *(__half2*)&Ss[r*EPAD + nh*128 + c]     = h0;
                *(__half2*)&Ss[(r+8)*EPAD + nh*128 + c] = h1;
            }
        }
    }
    __syncthreads();

    // ---- PASS B: E1 halves + end2 fold ----
    int rt = tid >> 1, oh = tid & 1;       // rt row, oh*6.. outs
    float oacc[6];
    #pragma unroll
    for (int o = 0; o < 6; o++) oacc[o] = 0.f;

    for (int nh = 0; nh < 4; nh++) {
        float acc[2][8][4];
        #pragma unroll
        for (int mt = 0; mt < 2; mt++)
            #pragma unroll
            for (int nt = 0; nt < 8; nt++)
                #pragma unroll
                for (int k = 0; k < 4; k++) acc[mt][nt][k] = 0.f;
        for (int kt = 0; kt < 4; kt++) {
            __syncthreads();
            #pragma unroll
            for (int i = 0; i < 4; i++) {
                int idx = tid + i*256;
                int r = idx >> 3, s = idx & 7;
                *(uint4*)&Bs[r*KPAD_H + s*8] =
                    *(const uint4*)&g_w1r[(nh*128 + r)*NSC + kt*64 + s*8];
            }
            __syncthreads();
            mma_block64(sSs + aLaneS + (uint32_t)(kt*64)*2, EPAD,
                        sBs + bLane + wnOff, acc);
        }
        // relu + e1 bias -> Es (fp16)
        #pragma unroll
        for (int mt = 0; mt < 2; mt++) {
            #pragma unroll
            for (int nt = 0; nt < 8; nt++) {
                int r = wm*32 + mt*16 + lq;
                int c = wn*64 + nt*8 + 2*lr;
                float b0 = e1b[nh*128 + c], b1 = e1b[nh*128 + c + 1];
                __half2 h0 = __floats2half2_rn(fmaxf(acc[mt][nt][0] + b0, 0.f),
                                               fmaxf(acc[mt][nt][1] + b1, 0.f));
                __half2 h1 = __floats2half2_rn(fmaxf(acc[mt][nt][2] + b0, 0.f),
                                               fmaxf(acc[mt][nt][3] + b1, 0.f));
                *(__half2*)&Es[r*136 + c]     = h0;
                *(__half2*)&Es[(r+8)*136 + c] = h1;
            }
        }
        // stage e2w slice [12][128]
        for (int i = tid; i < NOUT*128; i += 256)
            se2[i] = e2w[(i >> 7)*NEC + nh*128 + (i & 127)];
        __syncthreads();
        // fold: oacc[o] += sum_j Es[rt][j]*se2[oh*6+o][j]
        for (int j = 0; j < 128; j++) {
            float ev = __half2float(Es[rt*136 + j]);
            #pragma unroll
            for (int o = 0; o < 6; o++)
                oacc[o] += ev*se2[(oh*6 + o)*128 + j];
        }
        __syncthreads();
    }

    int grow = row0 + rt;
    int b = grow >> 11, v = grow & (NV - 1);
    #pragma unroll
    for (int o = 0; o < 6; o++) {
        int oo = oh*6 + o;
        out[((size_t)b*NOUT + oo)*NV + v] = oacc[o] + e2b[oo];
    }
}

// ---------------- adp = softmax(relu(nv1 @ nv2), axis=1) ----------------
__global__ void adp_kernel(const float* __restrict__ nv1, const float* __restrict__ nv2)
{
    int row = blockIdx.x;
    int tid = threadIdx.x;
    __shared__ float v1[10];
    __shared__ float red[256];
    if (tid < 10) v1[tid] = nv1[row*10 + tid];
    __syncthreads();
    float vals[8];
    float mx = -1e30f;
    #pragma unroll
    for (int j = 0; j < 8; j++) {
        int col = tid + j*256;
        float s = 0.f;
        #pragma unroll
        for (int k = 0; k < 10; k++) s += v1[k]*nv2[k*NV + col];
        s = fmaxf(s, 0.f);
        vals[j] = s;
        mx = fmaxf(mx, s);
    }
    red[tid] = mx; __syncthreads();
    for (int s2 = 128; s2 > 0; s2 >>= 1) {
        if (tid < s2) red[tid] = fmaxf(red[tid], red[tid+s2]);
        __syncthreads();
    }
    mx = red[0];
    __syncthreads();
    float sum = 0.f;
    #pragma unroll
    for (int j = 0; j < 8; j++) { vals[j] = expf(vals[j] - mx); sum += vals[j]; }
    red[tid] = sum; __syncthreads();
    for (int s2 = 128; s2 > 0; s2 >>= 1) {
        if (tid < s2) red[tid] += red[tid+s2];
        __syncthreads();
    }
    float inv = 1.f/red[0];
    #pragma unroll
    for (int j = 0; j < 8; j++) g_adp[row*NV + tid + j*256] = vals[j]*inv;
}

// ---------------- build fp16 transposed supports ----------------
__global__ void bt_kernel(const float* __restrict__ A)
{
    __shared__ float tile[32][33];
    int z = blockIdx.z;
    const float* S = (z < 2) ? (A + (size_t)z*NN) : g_adp;
    int r0 = blockIdx.y*32, c0 = blockIdx.x*32;
    int x = threadIdx.x & 31, y = threadIdx.x >> 5;
    #pragma unroll
    for (int i = 0; i < 32; i += 8)
        tile[y+i][x] = S[(size_t)(r0 + y + i)*NV + c0 + x];
    __syncthreads();
    #pragma unroll
    for (int i = 0; i < 32; i += 8)
        g_bt[((size_t)z*NV + c0 + y + i)*NV + r0 + x] = __float2half(tile[x][y+i]);
}

// ---------------- merged one-time weight prep ----------------
__global__ void prep_kernel(const float* __restrict__ gcnw,
                            const float* __restrict__ sw, const float* __restrict__ sb,
                            const float* __restrict__ fw, const float* __restrict__ gw,
                            const float* __restrict__ e1w)
{
    int idx = blockIdx.x*256 + threadIdx.x;
    if (idx < NLAY*NRC*224) {
        g_wg[idx] = __float2half(gcnw[idx]);
        return;
    }
    idx -= NLAY*NRC*224;
    if (idx < NSC*NSC) {
        int j = idx >> 8, k = idx & 255;
        int l = k >> 5, c = k & 31;
        g_wsk[idx] = __float2half(sw[(l*NSC + j)*NRC + c]);
        if (idx < NSC) {
            float s = 0.f;
            #pragma unroll
            for (int ll = 0; ll < NLAY; ll++) s += sb[ll*NSC + idx];
            g_bsk[idx] = s;
        }
        return;
    }
    idx -= NSC*NSC;
    if (idx < NLAY*64*64) {
        int l = idx >> 12, rem = idx & 4095;
        int q = rem >> 6, k = rem & 63;
        int o = q >> 1, isg = q & 1;
        int c = k >> 1, tap = k & 1;
        const float* W = isg ? gw : fw;
        g_wf[idx] = __float2half(W[((l*NRC + o)*NRC + c)*2 + tap]);
        return;
    }
    idx -= NLAY*64*64;
    if (idx < NEC*NSC)
        g_w1r[idx] = __float2half(e1w[idx]);
}
#define PREP_TOTAL (NLAY*NRC*224 + NSC*NSC + NLAY*64*64 + NEC*NSC)

// ---------------- pad + start 1x1 conv ----------------
__global__ void start_kernel(const float* __restrict__ x,
                             const float* __restrict__ sw, const float* __restrict__ sb)
{
    int v = blockIdx.x*256 + threadIdx.x;
    int t = blockIdx.y, b = blockIdx.z;
    float in0 = 0.f, in1 = 0.f;
    if (t > 0) {
        in0 = x[((b*2+0)*NV + v)*12 + (t-1)];
        in1 = x[((b*2+1)*NV + v)*12 + (t-1)];
    }
    #pragma unroll
    for (int o = 0; o < NRC; o++) {
        g_xa[((b*NRC+o)*13 + t)*NV + v] = sb[o] + sw[o*2]*in0 + sw[o*2+1]*in1;
    }
}

// ---------------- gated dilated conv via HMMA ----------------
#define GPAD 72
__global__ void __launch_bounds__(256) gated_mma(
    const float* __restrict__ fb, const float* __restrict__ gb,
    int layer, int Tin, int d, int parity)
{
    __shared__ __half Xs[128*GPAD];
    __shared__ __half Ws[64*GPAD];
    __shared__ __half Os[32*136];
    __shared__ float sfb[NRC], sgb[NRC];

    const float* xin = parity ? g_xb : g_xa;
    int Tout = Tin - d;
    int v0 = blockIdx.x*128;
    int t = blockIdx.y, b = blockIdx.z;
    int tid = threadIdx.x, wid = tid >> 5, lane = tid & 31;
    int lq = lane >> 2, lr = lane & 3;
    int lane15 = lane & 15, laneh = lane >> 4;

    const __half* wsrc = g_wf + layer*64*64;
    for (int i = tid; i < 64*32; i += 256) {
        int row = i >> 5, col2 = (i & 31)*2;
        *(uint32_t*)&Ws[row*GPAD + col2] = *(const uint32_t*)&wsrc[row*64 + col2];
    }
    if (tid < NRC) {
        sfb[tid] = fb[layer*NRC + tid];
        sgb[tid] = gb[layer*NRC + tid];
    }
    {
        int v = tid & 127;
        #pragma unroll
        for (int i = 0; i < 32; i++) {
            int r = i*2 + (tid >> 7);
            int c = r >> 1, tap = r & 1;
            float val = xin[((b*NRC + c)*Tin + t + tap*d)*NV + v0 + v];
            Xs[v*GPAD + r] = __float2half(val);
        }
    }
    __syncthreads();

    uint32_t sx = smem_u32(Xs), sw_ = smem_u32(Ws);
    float acc[8][4];
    #pragma unroll
    for (int nt = 0; nt < 8; nt++)
        #pragma unroll
        for (int k = 0; k < 4; k++) acc[nt][k] = 0.f;

    uint32_t axa = sx + (uint32_t)((wid*16 + lane15)*GPAD + 8*laneh)*2;
    uint32_t bxa = sw_ + (uint32_t)(lane15*GPAD + 8*laneh)*2;

    #pragma unroll
    for (int k16 = 0; k16 < 4; k16++) {
        uint32_t kk = (uint32_t)(k16*16)*2;
        uint32_t a0, a1, a2, a3;
        ldsm_x4(a0, a1, a2, a3, axa + kk);
        uint32_t bfr[8][2];
        #pragma unroll
        for (int nt2 = 0; nt2 < 4; nt2++) {
            uint32_t r0, r1, r2, r3;
            ldsm_x4(r0, r1, r2, r3, bxa + (uint32_t)(nt2*16*GPAD)*2 + kk);
            bfr[2*nt2][0] = r0; bfr[2*nt2+1][0] = r1;
            bfr[2*nt2][1] = r2; bfr[2*nt2+1][1] = r3;
        }
        #pragma unroll
        for (int nt = 0; nt < 8; nt++)
            mma_f16_16x8x16(acc[nt][0], acc[nt][1], acc[nt][2], acc[nt][3],
                            a0, a1, a2, a3, bfr[nt][0], bfr[nt][1]);
    }

    #pragma unroll
    for (int nt = 0; nt < 8; nt++) {
        int o = nt*4 + lr;
        float fbv = sfb[o], gbv = sgb[o];
        float f0 = tanh_fast(acc[nt][0] + fbv);
        float g0 = 0.5f*tanh_fast(0.5f*(acc[nt][1] + gbv)) + 0.5f;
        float f1 = tanh_fast(acc[nt][2] + fbv);
        float g1 = 0.5f*tanh_fast(0.5f*(acc[nt][3] + gbv)) + 0.5f;
        Os[o*136 + wid*16 + lq]     = __float2half(f0*g0);
        Os[o*136 + wid*16 + lq + 8] = __float2half(f1*g1);
    }
    __syncthreads();

    #pragma unroll
    for (int i = 0; i < 2; i++) {
        int idx = tid + i*256;
        int row = idx >> 4, ch = idx & 15;
        uint4 val = *(const uint4*)&Os[row*136 + ch*8];
        *(uint4*)&g_gx[((size_t)(b*NRC + row)*Tout + t)*NV + v0 + ch*8] = val;
    }
    if (t == Tout - 1) {
        int v = tid >> 1, oh = tid & 1;
        __half hb[16];
        #pragma unroll
        for (int i = 0; i < 16; i++) hb[i] = Os[(oh*16 + i)*136 + v];
        uint4* dst = (uint4*)(g_gxl + ((size_t)b*NV + v0 + v)*NSC + layer*NRC + oh*16);
        const uint4* src = (const uint4*)hb;
        dst[0] = src[0]; dst[1] = src[1];
    }
}

// ---------------- gcn via HMMA, k-major staging + ldmatrix.trans ----------------
#define XKROW 136
#define WPAD 232
#define GCN_SMEM (224*XKROW*2 + 32*WPAD*2 + 32*132*4 + 512)

__global__ void __launch_bounds__(256) gcn_mma(
    const float* __restrict__ gb,
    const float* __restrict__ bng, const float* __restrict__ bnb,
    const float* __restrict__ bnm, const float* __restrict__ bnv,
    int layer, int Tin, int d, int parity)
{
    extern __shared__ __half dsm[];
    __half* Xk = dsm;
    __half* Ws = dsm + 224*XKROW;
    float*  Os = (float*)(dsm + 224*XKROW + 32*WPAD);
    float*  cst = Os + 32*132;

    int Tout = Tin - d;
    const float* xin  = parity ? g_xb : g_xa;
    float*       xout = parity ? g_xa : g_xb;
    int v0 = blockIdx.x*128;
    int t = blockIdx.y, b = blockIdx.z;
    int tid = threadIdx.x, wid = tid >> 5, lane = tid & 31;
    int lq = lane >> 2, lr = lane & 3;
    int lane15 = lane & 15, laneh = lane >> 4;

    const __half* wsrc = g_wg + layer*NRC*224;
    for (int i = tid; i < 32*28; i += 256) {
        int o = i / 28, c = i % 28;
        *(uint4*)&Ws[o*WPAD + c*8] = *(const uint4*)&wsrc[o*224 + c*8];
    }
    if (tid < NRC) {
        cst[tid]      = bng[layer*NRC+tid]*rsqrtf(bnv[layer*NRC+tid] + 1e-5f);
        cst[32 + tid] = bnb[layer*NRC+tid];
        cst[64 + tid] = bnm[layer*NRC+tid];
        cst[96 + tid] = gb [layer*NRC+tid];
    }

    {
        #pragma unroll
        for (int i = 0; i < 14; i++) {
            int idx = tid + i*256;
            int vq = idx & 15, gc = idx >> 4;
            int g = gc >> 5, cc = gc & 31;
            const __half* Hp = (g == 0) ? g_gx : (g_H + (size_t)(g-1)*HBUF);
            uint4 val = *(const uint4*)(Hp + ((size_t)(b*NRC + cc)*Tout + t)*NV + v0 + vq*8);
            *(uint4*)&Xk[gc*XKROW + vq*8] = val;
        }
    }
    __syncthreads();

    uint32_t sxk = smem_u32(Xk), sw_ = smem_u32(Ws);
    float acc[4][4];
    #pragma unroll
    for (int nt = 0; nt < 4; nt++)
        #pragma unroll
        for (int k = 0; k < 4; k++) acc[nt][k] = 0.f;

    int ka = (lane & 7) + 8*((lane >> 4) & 1);
    int va = wid*16 + 8*((lane >> 3) & 1);
    uint32_t axk = sxk + (uint32_t)(ka*XKROW + va)*2;
    uint32_t bxa = sw_ + (uint32_t)(lane15*WPAD + 8*laneh)*2;

    #pragma unroll
    for (int kc = 0; kc < 14; kc++) {
        uint32_t a0, a1, a2, a3;
        ldsm_x4_t(a0, a1, a2, a3, axk + (uint32_t)(kc*16*XKROW)*2);
        uint32_t bfr[4][2];
        #pragma unroll
        for (int nt2 = 0; nt2 < 2; nt2++) {
            uint32_t r0, r1, r2, r3;
            ldsm_x4(r0, r1, r2, r3, bxa + (uint32_t)(nt2*16*WPAD + kc*16)*2);
            bfr[2*nt2][0] = r0; bfr[2*nt2+1][0] = r1;
            bfr[2*nt2][1] = r2; bfr[2*nt2+1][1] = r3;
        }
        #pragma unroll
        for (int nt = 0; nt < 4; nt++)
            mma_f16_16x8x16(acc[nt][0], acc[nt][1], acc[nt][2], acc[nt][3],
                            a0, a1, a2, a3, bfr[nt][0], bfr[nt][1]);
    }

    #pragma unroll
    for (int nt = 0; nt < 4; nt++) {
        int o = nt*8 + 2*lr;
        int v = wid*16 + lq;
        Os[o*132 + v]         = acc[nt][0];
        Os[(o+1)*132 + v]     = acc[nt][1];
        Os[o*132 + v + 8]     = acc[nt][2];
        Os[(o+1)*132 + v + 8] = acc[nt][3];
    }
    __syncthreads();

    #pragma unroll
    for (int i = 0; i < 16; i++) {
        int idx = tid + i*256;
        int o = idx >> 7, v = idx & 127;
        float val = Os[o*132 + v] + cst[96 + o]
                  + xin[((size_t)(b*NRC + o)*Tin + t + d)*NV + v0 + v];
        val = (val - cst[64 + o])*cst[o] + cst[32 + o];
        xout[((size_t)(b*NRC + o)*Tout + t)*NV + v0 + v] = val;
    }
}

// ---------------- launch ----------------
extern "C" void kernel_launch(void* const* d_in, const int* in_sizes, int n_in,
                              void* d_out, int out_size)
{
    (void)in_sizes; (void)n_in; (void)out_size;
    const float* x    = (const float*)d_in[0];
    const float* A    = (const float*)d_in[1];
    const float* nv1  = (const float*)d_in[2];
    const float* nv2  = (const float*)d_in[3];
    const float* fw   = (const float*)d_in[4];
    const float* fb   = (const float*)d_in[5];
    const float* gw   = (const float*)d_in[6];
    const float* gb   = (const float*)d_in[7];
    const float* sw   = (const float*)d_in[8];
    const float* sb   = (const float*)d_in[9];
    const float* gcnw = (const float*)d_in[10];
    const float* gcnb = (const float*)d_in[11];
    const float* bng  = (const float*)d_in[12];
    const float* bnb  = (const float*)d_in[13];
    const float* bnm  = (const float*)d_in[14];
    const float* bnv  = (const float*)d_in[15];
    const float* stw  = (const float*)d_in[16];
    const float* stb  = (const float*)d_in[17];
    const float* e1w  = (const float*)d_in[18];
    const float* e1b  = (const float*)d_in[19];
    const float* e2w  = (const float*)d_in[20];
    const float* e2b  = (const float*)d_in[21];

    __half *p_gx, *p_H, *p_bt;
    cudaGetSymbolAddress((void**)&p_gx,   g_gx);
    cudaGetSymbolAddress((void**)&p_H,    g_H);
    cudaGetSymbolAddress((void**)&p_bt,   g_bt);

    cudaFuncSetAttribute(mma_gemm, cudaFuncAttributeMaxDynamicSharedMemorySize, GSMEM);
    cudaFuncSetAttribute(gcn_mma,  cudaFuncAttributeMaxDynamicSharedMemorySize, GCN_SMEM);
    cudaFuncSetAttribute(end_fused, cudaFuncAttributeMaxDynamicSharedMemorySize, ESMEM);

    adp_kernel<<<NV, 256>>>(nv1, nv2);
    bt_kernel<<<dim3(NV/32, NV/32, 3), 256>>>(A);
    prep_kernel<<<(PREP_TOTAL + 255)/256, 256>>>(gcnw, sw, sb, fw, gw, e1w);
    start_kernel<<<dim3(NV/256, 13, NB), 256>>>(x, stw, stb);

    const int dil[NLAY] = {1,2,1,2,1,2,1,2};
    int Tin = 13, parity = 0;
    for (int i = 0; i < NLAY; i++) {
        int d = dil[i], Tout = Tin - d;
        gated_mma<<<dim3(NV/128, Tout, NB), 256>>>(fb, gb, i, Tin, d, parity);

        if (i < NLAY-1) {   // last layer's gcn output is dead code
            int M = NB*NRC*Tout;
            mma_gemm<<<dim3(NV/BN, M/BM, 3), 256, GSMEM>>>(
                p_gx, p_bt, p_H,
                0L, (long)NN, 2L*HBUF,
                NV, NV, NV, NV/BK, nullptr, 4);
            mma_gemm<<<dim3(NV/BN, M/BM, 3), 256, GSMEM>>>(
                p_H, p_bt, p_H + HBUF,
                2L*HBUF, (long)NN, 2L*HBUF,
                NV, NV, NV, NV/BK, nullptr, 4);
            gcn_mma<<<dim3(NV/128, Tout, NB), 256, GCN_SMEM>>>(
                gcnb, bng, bnb, bnm, bnv, i, Tin, d, parity);
        }
        parity ^= 1;
        Tin = Tout;
    }

    end_fused<<<(NB*NV)/128, 256, ESMEM>>>(e1b, e2w, e2b, (float*)d_out);
}